// round 12
// baseline (speedup 1.0000x reference)
#include <cuda_runtime.h>
#include <cuda_bf16.h>
#include <stdint.h>
#include <math.h>

#define BB 16
#define TT 2048
#define DD 256

// Certification threshold: computed (bf16-mma) lower bound on a row/col max.
// tanh saturates to exactly 1.0f for x >= ~9.0; bf16 pipeline error << 0.6,
// so a computed bound >= 9.6 certifies saturation of that row/col max.
#define CERT_THRESH 9.6f

// ---------------- scratch (static __device__ arrays; no runtime allocation) ----
__device__ __nv_bfloat16 g_qb[BB*TT*DD];    // q in bf16
__device__ __nv_bfloat16 g_ab[BB*TT*DD];    // a in bf16
__device__ __nv_bfloat16 g_Ut[DD*DD];       // U^T in bf16 (Ut[e][d] = U[d][e])
__device__ __nv_bfloat16 g_Ub[DD*DD];       // U in bf16 (row-major)
__device__ __nv_bfloat16 g_qU[BB*TT*DD];    // qU in bf16 (rows {0,1}/batch + gated rest)
__device__ __nv_bfloat16 g_Wt[BB*256*DD];   // Wt[b][j][d] = sum_e a[b,j,e]*U[d,e]
__device__ unsigned      g_rmax[BB*TT];     // encoded float max per q-row
__device__ unsigned      g_cmax[BB*TT];     // encoded float max per a-col
__device__ float         g_meanpart[1024*4*DD]; // per-(chunk,rowgroup) mean partials
__device__ float         g_mean2[1024*DD];  // stage-1 reduced mean partials (per slot)
__device__ int           g_need_full;       // 0 = certified (means exact)

// ---------------- helpers ----------------
__device__ __forceinline__ uint32_t smem_u32(const void* p) {
    uint32_t r;
    asm("{ .reg .u64 t; cvta.to.shared.u64 t, %1; cvt.u32.u64 %0, t; }"
        : "=r"(r) : "l"(p));
    return r;
}

__device__ __forceinline__ void cpasync16(uint32_t s, const void* g) {
    asm volatile("cp.async.cg.shared.global [%0], [%1], 16;" :: "r"(s), "l"(g) : "memory");
}
#define CP_COMMIT() asm volatile("cp.async.commit_group;" ::: "memory")
#define CP_WAIT0()  asm volatile("cp.async.wait_group 0;" ::: "memory")
#define CP_WAIT1()  asm volatile("cp.async.wait_group 1;" ::: "memory")

__device__ __forceinline__ void ldmx4(uint32_t addr, uint32_t& r0, uint32_t& r1,
                                      uint32_t& r2, uint32_t& r3) {
    asm volatile("ldmatrix.sync.aligned.m8n8.x4.shared.b16 {%0,%1,%2,%3}, [%4];"
                 : "=r"(r0), "=r"(r1), "=r"(r2), "=r"(r3) : "r"(addr));
}

__device__ __forceinline__ void mma16816(float* c, uint32_t a0, uint32_t a1,
                                         uint32_t a2, uint32_t a3,
                                         uint32_t b0, uint32_t b1) {
    asm volatile(
        "mma.sync.aligned.m16n8k16.row.col.f32.bf16.bf16.f32 "
        "{%0,%1,%2,%3}, {%4,%5,%6,%7}, {%8,%9}, {%0,%1,%2,%3};"
        : "+f"(c[0]), "+f"(c[1]), "+f"(c[2]), "+f"(c[3])
        : "r"(a0), "r"(a1), "r"(a2), "r"(a3), "r"(b0), "r"(b1));
}

__device__ __forceinline__ unsigned encf(float f) {
    unsigned u = __float_as_uint(f);
    return (u & 0x80000000u) ? ~u : (u | 0x80000000u);
}
__device__ __forceinline__ float decf(unsigned e) {
    unsigned u = (e & 0x80000000u) ? (e & 0x7FFFFFFFu) : ~e;
    return __uint_as_float(u);
}

// ---------------- GEMM core: C[128x128] = A[128x256] * B[128x256]^T -----------
// 2-stage double buffer (proven config; 3-stage regressed — L2-service-bound).
#define GEMM_SMEM 65536

__device__ __forceinline__ void load_chunk(uint32_t smb, int buf,
                                           const __nv_bfloat16* __restrict__ A,
                                           const __nv_bfloat16* __restrict__ Bm,
                                           int ck, int tid) {
    const __nv_bfloat16* Ac = A + ck * 64;
    const __nv_bfloat16* Bc = Bm + ck * 64;
    #pragma unroll
    for (int i = 0; i < 4; i++) {
        int v = tid + i * 256;
        int row = v >> 3, kv = v & 7;
        uint32_t o = (uint32_t)row * 128u + (uint32_t)kv * 16u;
        o ^= (o >> 3) & 0x70u;
        const size_t goff = (size_t)row * DD + (size_t)kv * 8;
        cpasync16(smb + buf * 16384 + o, Ac + goff);
        cpasync16(smb + 32768 + buf * 16384 + o, Bc + goff);
    }
}

// Single-sync double-buffered pipeline:
//   wait(chunk ck) -> syncthreads -> prefetch ck+1 -> compute ck
// Entry __syncthreads() protects back-to-back calls (loop-tiled callers).
__device__ __forceinline__ void gemm_mainloop(uint32_t smb, const __nv_bfloat16* A,
                                              const __nv_bfloat16* Bm, int tid,
                                              float acc[4][4][4]) {
    const int lid = tid & 31, w = tid >> 5;
    const int wm = (w >> 2) * 64, wn = (w & 3) * 32;
    const int lrow = lid & 15;
    const uint32_t khalf = (uint32_t)(lid >> 4) * 16u;

    __syncthreads();
    load_chunk(smb, 0, A, Bm, 0, tid);
    CP_COMMIT();

    #pragma unroll
    for (int ck = 0; ck < 4; ck++) {
        CP_WAIT0();
        __syncthreads();
        if (ck + 1 < 4) {
            load_chunk(smb, (ck + 1) & 1, A, Bm, ck + 1, tid);
            CP_COMMIT();
        }

        const uint32_t abase = smb + (ck & 1) * 16384;
        const uint32_t bbase = smb + 32768 + (ck & 1) * 16384;

        #pragma unroll
        for (int kk = 0; kk < 4; kk++) {
            const uint32_t koff = (uint32_t)kk * 32u + khalf;
            uint32_t a[4][4];
            #pragma unroll
            for (int mt = 0; mt < 4; mt++) {
                uint32_t o = (uint32_t)(wm + mt * 16 + lrow) * 128u + koff;
                o ^= (o >> 3) & 0x70u;
                ldmx4(abase + o, a[mt][0], a[mt][1], a[mt][2], a[mt][3]);
            }
            uint32_t b[4][2];
            #pragma unroll
            for (int np = 0; np < 2; np++) {
                uint32_t o = (uint32_t)(wn + np * 16 + lrow) * 128u + koff;
                o ^= (o >> 3) & 0x70u;
                uint32_t r0, r1, r2, r3;
                ldmx4(bbase + o, r0, r1, r2, r3);
                b[np * 2 + 0][0] = r0; b[np * 2 + 0][1] = r2;
                b[np * 2 + 1][0] = r1; b[np * 2 + 1][1] = r3;
            }
            #pragma unroll
            for (int mt = 0; mt < 4; mt++)
                #pragma unroll
                for (int nt = 0; nt < 4; nt++)
                    mma16816(acc[mt][nt], a[mt][0], a[mt][1], a[mt][2], a[mt][3],
                             b[nt][0], b[nt][1]);
        }
    }
}

// shared epilogues ------------------------------------------------------------
__device__ __forceinline__ void epi_store_bf16(const float acc[4][4][4], int tid,
                                               __nv_bfloat16* dstbase, int rowOff,
                                               int colOff, int rowStride) {
    const int lid = tid & 31, w = tid >> 5;
    const int wm = (w >> 2) * 64, wn = (w & 3) * 32;
    const int g = lid >> 2, tg = lid & 3;
    #pragma unroll
    for (int mt = 0; mt < 4; mt++) {
        int row0 = rowOff + wm + mt * 16 + g;
        #pragma unroll
        for (int nt = 0; nt < 4; nt++) {
            int col = colOff + wn + nt * 8 + 2 * tg;
            __nv_bfloat162 p0 = __floats2bfloat162_rn(acc[mt][nt][0], acc[mt][nt][1]);
            __nv_bfloat162 p1 = __floats2bfloat162_rn(acc[mt][nt][2], acc[mt][nt][3]);
            *reinterpret_cast<unsigned*>(dstbase + (size_t)row0 * rowStride + col) =
                *reinterpret_cast<unsigned*>(&p0);
            *reinterpret_cast<unsigned*>(dstbase + (size_t)(row0 + 8) * rowStride + col) =
                *reinterpret_cast<unsigned*>(&p1);
        }
    }
}

__device__ __forceinline__ void epi_max(const float acc[4][4][4], int tid,
                                        int rowBase, int colBase) {
    const int lid = tid & 31, w = tid >> 5;
    const int wm = (w >> 2) * 64, wn = (w & 3) * 32;
    const int g = lid >> 2, tg = lid & 3;
    const int rb = rowBase + wm;
    const int cb = colBase + wn;

    #pragma unroll
    for (int mt = 0; mt < 4; mt++) {
        float r0 = -3.0e38f, r1 = -3.0e38f;
        #pragma unroll
        for (int nt = 0; nt < 4; nt++) {
            r0 = fmaxf(r0, fmaxf(acc[mt][nt][0], acc[mt][nt][1]));
            r1 = fmaxf(r1, fmaxf(acc[mt][nt][2], acc[mt][nt][3]));
        }
        r0 = fmaxf(r0, __shfl_xor_sync(0xffffffffu, r0, 1));
        r0 = fmaxf(r0, __shfl_xor_sync(0xffffffffu, r0, 2));
        r1 = fmaxf(r1, __shfl_xor_sync(0xffffffffu, r1, 1));
        r1 = fmaxf(r1, __shfl_xor_sync(0xffffffffu, r1, 2));
        if (tg == 0) {
            atomicMax(&g_rmax[rb + mt * 16 + g], encf(r0));
            atomicMax(&g_rmax[rb + mt * 16 + g + 8], encf(r1));
        }
    }
    #pragma unroll
    for (int nt = 0; nt < 4; nt++) {
        float c0 = -3.0e38f, c1 = -3.0e38f;
        #pragma unroll
        for (int mt = 0; mt < 4; mt++) {
            c0 = fmaxf(c0, fmaxf(acc[mt][nt][0], acc[mt][nt][2]));
            c1 = fmaxf(c1, fmaxf(acc[mt][nt][1], acc[mt][nt][3]));
        }
        #pragma unroll
        for (int s = 4; s < 32; s <<= 1) {
            c0 = fmaxf(c0, __shfl_xor_sync(0xffffffffu, c0, s));
            c1 = fmaxf(c1, __shfl_xor_sync(0xffffffffu, c1, s));
        }
        if (g == 0) {
            atomicMax(&g_cmax[cb + nt * 8 + 2 * tg], encf(c0));
            atomicMax(&g_cmax[cb + nt * 8 + 2 * tg + 1], encf(c1));
        }
    }
}

#define ACC_DECL_ZERO(acc) \
    float acc[4][4][4]; \
    _Pragma("unroll") for (int _i = 0; _i < 4; _i++) \
    _Pragma("unroll") for (int _j = 0; _j < 4; _j++) \
    _Pragma("unroll") for (int _r = 0; _r < 4; _r++) acc[_i][_j][_r] = 0.0f;

// ---------------- k0: convert fp32->bf16 + mean partials + aux ---------------
// bx < 1024: convert 64-row chunks (q: bx<512, a: 512..1023). No smem ->
// high occupancy, BW-bound (lesson: converts must not share a GEMM smem config).
// bx in [1024,1088): 64 zero blocks; [1088,1096): 8 U blocks (4 Ut + 4 Ub).
__global__ void __launch_bounds__(256) k0_convert(const float* __restrict__ q,
                                                  const float* __restrict__ a,
                                                  const float* __restrict__ U) {
    int bx = blockIdx.x;
    int tid = threadIdx.x;

    if (bx >= 1024) {
        int bz = bx - 1024;
        if (bz < 64) {
            int i0 = (bz * 256 + tid) * 2;
            g_rmax[i0] = 0u; g_rmax[i0 + 1] = 0u;
            g_cmax[i0] = 0u; g_cmax[i0 + 1] = 0u;
            if (bz == 0 && tid == 0) g_need_full = 0;
        } else if (bz < 68) {
            int blk = bz - 64;   // Ut
            #pragma unroll 4
            for (int it = 0; it < 64; it++) {
                int i = blk * 16384 + it * 256 + tid;
                int d = i >> 8, e = i & 255;
                g_Ut[e * DD + d] = __float2bfloat16(U[i]);
            }
        } else {
            int blk = bz - 68;   // Ub (straight)
            #pragma unroll 4
            for (int it = 0; it < 64; it++) {
                int i = blk * 16384 + it * 256 + tid;
                g_Ub[i] = __float2bfloat16(U[i]);
            }
        }
        return;
    }

    int tensor = bx >> 9;
    int local = bx & 511;
    int b = local >> 5;
    int chunk = local & 31;   // 64-row chunk
    const float4* src = (const float4*)((tensor ? a : q) +
                        ((size_t)b * TT + (size_t)chunk * 64) * DD);
    uint2* dst = (uint2*)((tensor ? g_ab : g_qb) +
                 ((size_t)b * TT + (size_t)chunk * 64) * DD);

    const int dvec = tid & 63;          // float4 index within row
    const int rg = tid >> 6;            // row group 0..3
    float4 s = make_float4(0.f, 0.f, 0.f, 0.f);
    #pragma unroll 4
    for (int it = 0; it < 16; it++) {
        int row = it * 4 + rg;
        float4 v = src[(size_t)row * 64 + dvec];
        s.x += v.x; s.y += v.y; s.z += v.z; s.w += v.w;
        __nv_bfloat162 lo = __floats2bfloat162_rn(v.x, v.y);
        __nv_bfloat162 hi = __floats2bfloat162_rn(v.z, v.w);
        uint2 o;
        o.x = *reinterpret_cast<unsigned*>(&lo);
        o.y = *reinterpret_cast<unsigned*>(&hi);
        dst[(size_t)row * 64 + dvec] = o;
    }
    float4* mp = (float4*)&g_meanpart[((size_t)bx * 4 + rg) * DD];
    mp[dvec] = s;
}

// ---------------- kWqa: kW tiles + k1a tiles (one launch, 128 CTAs) -----------
// bid: b = bid>>3, s = bid&7. s<4: kW (tileM=s>>1, tileN=s&1).
// s>=4: k1a (mi=(s-4)>>1, tileN=(s-4)&1).
__global__ void __launch_bounds__(256, 2) kWqa() {
    extern __shared__ char sm[];
    uint32_t smb = smem_u32(sm);
    int tid = threadIdx.x;
    int b = blockIdx.x >> 3;
    int s = blockIdx.x & 7;

    ACC_DECL_ZERO(acc);
    if (s < 4) {
        int tileM = s >> 1, tileN = s & 1;
        gemm_mainloop(smb, g_ab + ((size_t)b * TT + (size_t)tileM * 128) * DD,
                      g_Ub + (size_t)tileN * 128 * DD, tid, acc);
        epi_store_bf16(acc, tid, g_Wt + (size_t)b * 256 * DD,
                       tileM * 128, tileN * 128, DD);
    } else {
        int mi = (s - 4) >> 1, tileN = (s - 4) & 1;
        gemm_mainloop(smb, g_qb + (size_t)(b * 16 + mi) * 128 * DD,
                      g_Ut + (size_t)tileN * 128 * DD, tid, acc);
        epi_store_bf16(acc, tid, g_qU, (b * 16 + mi) * 128, tileN * 128, DD);
    }
}

// ---------------- kCert: kG_sample + col-cert (one launch, 960 CTAs) ----------
// bid: b = bid/60, s = bid%60. s<32: kG (j=s>>1, tileN=s&1): row samples for
// all rows + exact col maxes 0..255. s>=32: col-cert (nj=2+(g>>1), mi=g&1).
__global__ void __launch_bounds__(256, 2) kCert() {
    extern __shared__ char sm[];
    uint32_t smb = smem_u32(sm);
    int tid = threadIdx.x;
    int b = blockIdx.x / 60;
    int s = blockIdx.x % 60;

    ACC_DECL_ZERO(acc);
    if (s < 32) {
        int j = s >> 1, tileN = s & 1;
        gemm_mainloop(smb, g_qb + (size_t)(b * 16 + j) * 128 * DD,
                      g_Wt + (size_t)b * 256 * DD + (size_t)tileN * 128 * DD, tid, acc);
        epi_max(acc, tid, (b * 16 + j) * 128, b * TT + tileN * 128);
    } else {
        int g = s - 32;
        int nj = 2 + (g >> 1), mi = g & 1;
        gemm_mainloop(smb, g_qU + ((size_t)b * TT + (size_t)mi * 128) * DD,
                      g_ab + ((size_t)b * TT + (size_t)nj * 128) * DD, tid, acc);
        epi_max(acc, tid, b * TT + mi * 128, b * TT + nj * 128);
    }
}

// ---------------- kCheckMean: cert check (vectorized) + mean stage-1 ----------
// bid<1024: sum the 4 rowgroup vectors of slot bid -> g_mean2[bid].
// bid in [1024,1056): check 8 elements/thread via uint4 x2.
__global__ void kCheckMean() {
    int bid = blockIdx.x;
    int tid = threadIdx.x;
    if (bid < 1024) {
        float s = 0.0f;
        #pragma unroll
        for (int rg = 0; rg < 4; rg++)
            s += g_meanpart[((size_t)bid * 4 + rg) * DD + tid];
        g_mean2[(size_t)bid * DD + tid] = s;
        return;
    }
    int base = ((bid - 1024) * 256 + tid) * 8;   // 0..65528, 8-aligned
    const uint4* src = (base < BB * TT)
        ? (const uint4*)&g_rmax[base]
        : (const uint4*)&g_cmax[base - BB * TT];
    uint4 v0 = src[0], v1 = src[1];
    unsigned m = v0.x;
    m = min(m, v0.y); m = min(m, v0.z); m = min(m, v0.w);
    m = min(m, v1.x); m = min(m, v1.y); m = min(m, v1.z); m = min(m, v1.w);
    if (decf(m) < CERT_THRESH) atomicOr(&g_need_full, 1);
}

// ---------------- k_out: certified path -> means (stage 2: 32 slots each) -----
__global__ void k_out_mean(float* __restrict__ out) {
    if (g_need_full) return;
    int i = blockIdx.x * 256 + threadIdx.x;   // 0..8191
    int which = i >> 12;
    int b = (i >> 8) & 15;
    int d = i & 255;
    int slot0 = which * 512 + b * 32;
    float s = 0.0f;
    #pragma unroll 8
    for (int j = 0; j < 32; j++) s += g_mean2[(size_t)(slot0 + j) * DD + d];
    out[i] = s * (1.0f / (float)TT);
}

// ---------------- gated fallback: complete qU (7 tiles per CTA) ---------------
__global__ void __launch_bounds__(256, 2) k1_qU_gated() {
    if (g_need_full == 0) return;
    extern __shared__ char sm[];
    uint32_t smb = smem_u32(sm);
    int tid = threadIdx.x;
    int tileN = blockIdx.x & 1;
    int group = blockIdx.x >> 1;   // 0..31
    for (int i = 0; i < 7; i++) {
        int y = group * 7 + i;     // 0..223
        int tileM = (y / 14) * 16 + 2 + (y % 14);
        ACC_DECL_ZERO(acc);
        gemm_mainloop(smb, g_qb + (size_t)tileM * 128 * DD,
                      g_Ut + (size_t)tileN * 128 * DD, tid, acc);
        epi_store_bf16(acc, tid, g_qU, tileM * 128, tileN * 128, DD);
    }
}

// ---------------- gated fallback: remaining G tiles (28 per CTA) ---------------
__global__ void __launch_bounds__(256, 2) k2_gated() {
    if (g_need_full == 0) return;
    extern __shared__ char sm[];
    uint32_t smb = smem_u32(sm);
    int tid = threadIdx.x;
    int nj = blockIdx.x + 2;
    int yy = blockIdx.y;           // 0..1
    int bq = blockIdx.z;           // 0..3
    for (int bl = 0; bl < 4; bl++) {
        int b = bq * 4 + bl;
        for (int i = 0; i < 7; i++) {
            int mi = 2 + yy * 7 + i;   // 2..15
            ACC_DECL_ZERO(acc);
            gemm_mainloop(smb, g_qU + ((size_t)b * TT + (size_t)mi * 128) * DD,
                          g_ab + ((size_t)b * TT + (size_t)nj * 128) * DD, tid, acc);
            epi_max(acc, tid, b * TT + mi * 128, b * TT + nj * 128);
        }
    }
}

// ---------------- gated fallback: softmax + pooling + output (ONE kernel) -----
// grid 32: which = bid>>4, b = bid&15. Softmax over the 2048 tanh'd maxes,
// weights staged in smem, then out[which,b,d] = sum_t w[t]*src[b,t,d].
__global__ void k3_fallback(const float* __restrict__ q, const float* __restrict__ a,
                            float* __restrict__ out) {
    if (g_need_full == 0) return;
    __shared__ float ws[TT];
    __shared__ float red[256];
    int tid = threadIdx.x;
    int which = blockIdx.x >> 4;
    int b = blockIdx.x & 15;
    const unsigned* src = (which ? g_cmax : g_rmax) + b * TT;

    float tv[8];
    #pragma unroll
    for (int i = 0; i < 8; i++) tv[i] = tanhf(decf(src[i * 256 + tid]));

    float lm = tv[0];
    #pragma unroll
    for (int i = 1; i < 8; i++) lm = fmaxf(lm, tv[i]);
    red[tid] = lm;
    __syncthreads();
    for (int s = 128; s > 0; s >>= 1) {
        if (tid < s) red[tid] = fmaxf(red[tid], red[tid + s]);
        __syncthreads();
    }
    float mx = red[0];
    __syncthreads();

    float ls = 0.0f;
    #pragma unroll
    for (int i = 0; i < 8; i++) ls += expf(tv[i] - mx);
    red[tid] = ls;
    __syncthreads();
    for (int s = 128; s > 0; s >>= 1) {
        if (tid < s) red[tid] += red[tid + s];
        __syncthreads();
    }
    float inv = 1.0f / red[0];
    __syncthreads();

    #pragma unroll
    for (int i = 0; i < 8; i++) ws[i * 256 + tid] = expf(tv[i] - mx) * inv;
    __syncthreads();

    // pooling: thread = d, deterministic serial sum over t (fallback-only path)
    const float* basep = (which ? a : q) + (size_t)b * TT * DD + tid;
    float acc = 0.0f;
    for (int t = 0; t < TT; t++) acc += ws[t] * basep[(size_t)t * DD];
    out[which * BB * DD + b * DD + tid] = acc;
}

// ---------------- launch ------------------------------------------------------
extern "C" void kernel_launch(void* const* d_in, const int* in_sizes, int n_in,
                              void* d_out, int out_size) {
    int ui = 2;
    for (int i = 0; i < n_in; i++)
        if (in_sizes[i] == DD * DD) ui = i;
    const float* ptrs[3];
    int k = 0;
    for (int i = 0; i < n_in && k < 3; i++)
        if (i != ui) ptrs[k++] = (const float*)d_in[i];
    const float* q = ptrs[0];
    const float* a = ptrs[1];
    const float* U = (const float*)d_in[ui];
    float* out = (float*)d_out;

    static int init_done = 0;
    if (!init_done) {
        cudaFuncSetAttribute(kWqa,        cudaFuncAttributeMaxDynamicSharedMemorySize, GEMM_SMEM);
        cudaFuncSetAttribute(kCert,       cudaFuncAttributeMaxDynamicSharedMemorySize, GEMM_SMEM);
        cudaFuncSetAttribute(k1_qU_gated, cudaFuncAttributeMaxDynamicSharedMemorySize, GEMM_SMEM);
        cudaFuncSetAttribute(k2_gated,    cudaFuncAttributeMaxDynamicSharedMemorySize, GEMM_SMEM);
        init_done = 1;
    }

    // converts + mean partials + U^T/U + zero maxes (no-smem, high occupancy)
    k0_convert<<<1096, 256>>>(q, a, U);
    // Wt tiles + qU rows {0,1}/batch (merged, 128 CTAs)
    kWqa<<<128, 256, GEMM_SMEM>>>();
    // kG_sample + col-cert (merged, 960 CTAs)
    kCert<<<960, 256, GEMM_SMEM>>>();
    // cert check (vectorized) + mean stage-1, then certified output
    kCheckMean<<<1056, 256>>>();
    k_out_mean<<<32, 256>>>(out);
    // fallback (self-disabled when certified; loop-tiled + merged tail)
    k1_qU_gated<<<64, 256, GEMM_SMEM>>>();
    k2_gated<<<dim3(14, 2, 4), 256, GEMM_SMEM>>>();
    k3_fallback<<<32, 256>>>(q, a, out);
    (void)out_size;
}

// round 13
// speedup vs baseline: 1.4040x; 1.4040x over previous
#include <cuda_runtime.h>
#include <cuda_bf16.h>
#include <stdint.h>
#include <math.h>

#define BB 16
#define TT 2048
#define DD 256

// Certification threshold: computed (bf16-mma) lower bound on a row/col max.
// tanh saturates to exactly 1.0f for x >= ~9.0; bf16 pipeline error << 0.6,
// so a computed bound >= 9.6 certifies saturation of that row/col max.
#define CERT_THRESH 9.6f

// ---------------- scratch (static __device__ arrays; no runtime allocation) ----
__device__ __nv_bfloat16 g_qb[BB*TT*DD];    // q in bf16
__device__ __nv_bfloat16 g_ab[BB*TT*DD];    // a in bf16
__device__ __nv_bfloat16 g_Ut[DD*DD];       // U^T in bf16 (Ut[e][d] = U[d][e])
__device__ __nv_bfloat16 g_Ub[DD*DD];       // U in bf16 (row-major)
__device__ __nv_bfloat16 g_qU[BB*TT*DD];    // qU in bf16 (rows {0,1}/batch + gated rest)
__device__ __nv_bfloat16 g_Wt[BB*256*DD];   // Wt[b][j][d] = sum_e a[b,j,e]*U[d,e]
__device__ unsigned      g_rmax[BB*TT];     // encoded float max per q-row
__device__ unsigned      g_cmax[BB*TT];     // encoded float max per a-col
__device__ float         g_wts[2*BB*TT];    // softmax weights (fallback)
__device__ float         g_part[2*BB*8*DD]; // pooling partials (fallback)
__device__ float         g_meanpart[1024*4*DD]; // per-(chunk,rowgroup) mean partials
__device__ float         g_mean2[256*DD];   // stage-1 reduced mean partials
__device__ int           g_need_full;       // 0 = certified (means exact)

// ---------------- helpers ----------------
__device__ __forceinline__ uint32_t smem_u32(const void* p) {
    uint32_t r;
    asm("{ .reg .u64 t; cvta.to.shared.u64 t, %1; cvt.u32.u64 %0, t; }"
        : "=r"(r) : "l"(p));
    return r;
}

__device__ __forceinline__ void cpasync16(uint32_t s, const void* g) {
    asm volatile("cp.async.cg.shared.global [%0], [%1], 16;" :: "r"(s), "l"(g) : "memory");
}
#define CP_COMMIT() asm volatile("cp.async.commit_group;" ::: "memory")
#define CP_WAIT0()  asm volatile("cp.async.wait_group 0;" ::: "memory")

__device__ __forceinline__ void ldmx4(uint32_t addr, uint32_t& r0, uint32_t& r1,
                                      uint32_t& r2, uint32_t& r3) {
    asm volatile("ldmatrix.sync.aligned.m8n8.x4.shared.b16 {%0,%1,%2,%3}, [%4];"
                 : "=r"(r0), "=r"(r1), "=r"(r2), "=r"(r3) : "r"(addr));
}

__device__ __forceinline__ void mma16816(float* c, uint32_t a0, uint32_t a1,
                                         uint32_t a2, uint32_t a3,
                                         uint32_t b0, uint32_t b1) {
    asm volatile(
        "mma.sync.aligned.m16n8k16.row.col.f32.bf16.bf16.f32 "
        "{%0,%1,%2,%3}, {%4,%5,%6,%7}, {%8,%9}, {%0,%1,%2,%3};"
        : "+f"(c[0]), "+f"(c[1]), "+f"(c[2]), "+f"(c[3])
        : "r"(a0), "r"(a1), "r"(a2), "r"(a3), "r"(b0), "r"(b1));
}

__device__ __forceinline__ unsigned encf(float f) {
    unsigned u = __float_as_uint(f);
    return (u & 0x80000000u) ? ~u : (u | 0x80000000u);
}
__device__ __forceinline__ float decf(unsigned e) {
    unsigned u = (e & 0x80000000u) ? (e & 0x7FFFFFFFu) : ~e;
    return __uint_as_float(u);
}

// ---------------- GEMM core: C[128x128] = A[128x256] * B[128x256]^T -----------
#define GEMM_SMEM 65536

__device__ __forceinline__ void load_chunk(uint32_t smb, int buf,
                                           const __nv_bfloat16* __restrict__ A,
                                           const __nv_bfloat16* __restrict__ Bm,
                                           int ck, int tid) {
    const __nv_bfloat16* Ac = A + ck * 64;
    const __nv_bfloat16* Bc = Bm + ck * 64;
    #pragma unroll
    for (int i = 0; i < 4; i++) {
        int v = tid + i * 256;
        int row = v >> 3, kv = v & 7;
        uint32_t o = (uint32_t)row * 128u + (uint32_t)kv * 16u;
        o ^= (o >> 3) & 0x70u;
        const size_t goff = (size_t)row * DD + (size_t)kv * 8;
        cpasync16(smb + buf * 16384 + o, Ac + goff);
        cpasync16(smb + 32768 + buf * 16384 + o, Bc + goff);
    }
}

// Single-sync double-buffered pipeline:
//   wait(chunk ck) -> syncthreads -> prefetch ck+1 -> compute ck
__device__ __forceinline__ void gemm_mainloop(uint32_t smb, const __nv_bfloat16* A,
                                              const __nv_bfloat16* Bm, int tid,
                                              float acc[4][4][4]) {
    const int lid = tid & 31, w = tid >> 5;
    const int wm = (w >> 2) * 64, wn = (w & 3) * 32;
    const int lrow = lid & 15;
    const uint32_t khalf = (uint32_t)(lid >> 4) * 16u;

    load_chunk(smb, 0, A, Bm, 0, tid);
    CP_COMMIT();

    #pragma unroll
    for (int ck = 0; ck < 4; ck++) {
        CP_WAIT0();
        __syncthreads();
        if (ck + 1 < 4) {
            load_chunk(smb, (ck + 1) & 1, A, Bm, ck + 1, tid);
            CP_COMMIT();
        }

        const uint32_t abase = smb + (ck & 1) * 16384;
        const uint32_t bbase = smb + 32768 + (ck & 1) * 16384;

        #pragma unroll
        for (int kk = 0; kk < 4; kk++) {
            const uint32_t koff = (uint32_t)kk * 32u + khalf;
            uint32_t a[4][4];
            #pragma unroll
            for (int mt = 0; mt < 4; mt++) {
                uint32_t o = (uint32_t)(wm + mt * 16 + lrow) * 128u + koff;
                o ^= (o >> 3) & 0x70u;
                ldmx4(abase + o, a[mt][0], a[mt][1], a[mt][2], a[mt][3]);
            }
            uint32_t b[4][2];
            #pragma unroll
            for (int np = 0; np < 2; np++) {
                uint32_t o = (uint32_t)(wn + np * 16 + lrow) * 128u + koff;
                o ^= (o >> 3) & 0x70u;
                uint32_t r0, r1, r2, r3;
                ldmx4(bbase + o, r0, r1, r2, r3);
                b[np * 2 + 0][0] = r0; b[np * 2 + 0][1] = r2;
                b[np * 2 + 1][0] = r1; b[np * 2 + 1][1] = r3;
            }
            #pragma unroll
            for (int mt = 0; mt < 4; mt++)
                #pragma unroll
                for (int nt = 0; nt < 4; nt++)
                    mma16816(acc[mt][nt], a[mt][0], a[mt][1], a[mt][2], a[mt][3],
                             b[nt][0], b[nt][1]);
        }
    }
}

// shared epilogues ------------------------------------------------------------
__device__ __forceinline__ void epi_store_bf16(const float acc[4][4][4], int tid,
                                               __nv_bfloat16* dstbase, int rowOff,
                                               int colOff, int rowStride) {
    const int lid = tid & 31, w = tid >> 5;
    const int wm = (w >> 2) * 64, wn = (w & 3) * 32;
    const int g = lid >> 2, tg = lid & 3;
    #pragma unroll
    for (int mt = 0; mt < 4; mt++) {
        int row0 = rowOff + wm + mt * 16 + g;
        #pragma unroll
        for (int nt = 0; nt < 4; nt++) {
            int col = colOff + wn + nt * 8 + 2 * tg;
            __nv_bfloat162 p0 = __floats2bfloat162_rn(acc[mt][nt][0], acc[mt][nt][1]);
            __nv_bfloat162 p1 = __floats2bfloat162_rn(acc[mt][nt][2], acc[mt][nt][3]);
            *reinterpret_cast<unsigned*>(dstbase + (size_t)row0 * rowStride + col) =
                *reinterpret_cast<unsigned*>(&p0);
            *reinterpret_cast<unsigned*>(dstbase + (size_t)(row0 + 8) * rowStride + col) =
                *reinterpret_cast<unsigned*>(&p1);
        }
    }
}

__device__ __forceinline__ void epi_max(const float acc[4][4][4], int tid,
                                        int rowBase, int colBase) {
    const int lid = tid & 31, w = tid >> 5;
    const int wm = (w >> 2) * 64, wn = (w & 3) * 32;
    const int g = lid >> 2, tg = lid & 3;
    const int rb = rowBase + wm;
    const int cb = colBase + wn;

    #pragma unroll
    for (int mt = 0; mt < 4; mt++) {
        float r0 = -3.0e38f, r1 = -3.0e38f;
        #pragma unroll
        for (int nt = 0; nt < 4; nt++) {
            r0 = fmaxf(r0, fmaxf(acc[mt][nt][0], acc[mt][nt][1]));
            r1 = fmaxf(r1, fmaxf(acc[mt][nt][2], acc[mt][nt][3]));
        }
        r0 = fmaxf(r0, __shfl_xor_sync(0xffffffffu, r0, 1));
        r0 = fmaxf(r0, __shfl_xor_sync(0xffffffffu, r0, 2));
        r1 = fmaxf(r1, __shfl_xor_sync(0xffffffffu, r1, 1));
        r1 = fmaxf(r1, __shfl_xor_sync(0xffffffffu, r1, 2));
        if (tg == 0) {
            atomicMax(&g_rmax[rb + mt * 16 + g], encf(r0));
            atomicMax(&g_rmax[rb + mt * 16 + g + 8], encf(r1));
        }
    }
    #pragma unroll
    for (int nt = 0; nt < 4; nt++) {
        float c0 = -3.0e38f, c1 = -3.0e38f;
        #pragma unroll
        for (int mt = 0; mt < 4; mt++) {
            c0 = fmaxf(c0, fmaxf(acc[mt][nt][0], acc[mt][nt][2]));
            c1 = fmaxf(c1, fmaxf(acc[mt][nt][1], acc[mt][nt][3]));
        }
        #pragma unroll
        for (int s = 4; s < 32; s <<= 1) {
            c0 = fmaxf(c0, __shfl_xor_sync(0xffffffffu, c0, s));
            c1 = fmaxf(c1, __shfl_xor_sync(0xffffffffu, c1, s));
        }
        if (g == 0) {
            atomicMax(&g_cmax[cb + nt * 8 + 2 * tg], encf(c0));
            atomicMax(&g_cmax[cb + nt * 8 + 2 * tg + 1], encf(c1));
        }
    }
}

#define ACC_DECL_ZERO(acc) \
    float acc[4][4][4]; \
    _Pragma("unroll") for (int _i = 0; _i < 4; _i++) \
    _Pragma("unroll") for (int _j = 0; _j < 4; _j++) \
    _Pragma("unroll") for (int _r = 0; _r < 4; _r++) acc[_i][_j][_r] = 0.0f;

// ---------------- k0: convert fp32->bf16 + mean partials + aux ---------------
// bx < 1024: convert 64-row chunks (q: bx<512, a: 512..1023). No smem ->
// high occupancy, BW-bound (lesson: converts must not share a GEMM smem config).
// bx in [1024,1088): 64 zero blocks; [1088,1096): 8 U blocks (4 Ut + 4 Ub).
__global__ void __launch_bounds__(256) k0_convert(const float* __restrict__ q,
                                                  const float* __restrict__ a,
                                                  const float* __restrict__ U) {
    int bx = blockIdx.x;
    int tid = threadIdx.x;

    if (bx >= 1024) {
        int bz = bx - 1024;
        if (bz < 64) {
            int i0 = (bz * 256 + tid) * 2;
            g_rmax[i0] = 0u; g_rmax[i0 + 1] = 0u;
            g_cmax[i0] = 0u; g_cmax[i0 + 1] = 0u;
            if (bz == 0 && tid == 0) g_need_full = 0;
        } else if (bz < 68) {
            int blk = bz - 64;   // Ut
            #pragma unroll 4
            for (int it = 0; it < 64; it++) {
                int i = blk * 16384 + it * 256 + tid;
                int d = i >> 8, e = i & 255;
                g_Ut[e * DD + d] = __float2bfloat16(U[i]);
            }
        } else {
            int blk = bz - 68;   // Ub (straight)
            #pragma unroll 4
            for (int it = 0; it < 64; it++) {
                int i = blk * 16384 + it * 256 + tid;
                g_Ub[i] = __float2bfloat16(U[i]);
            }
        }
        return;
    }

    int tensor = bx >> 9;
    int local = bx & 511;
    int b = local >> 5;
    int chunk = local & 31;   // 64-row chunk
    const float4* src = (const float4*)((tensor ? a : q) +
                        ((size_t)b * TT + (size_t)chunk * 64) * DD);
    uint2* dst = (uint2*)((tensor ? g_ab : g_qb) +
                 ((size_t)b * TT + (size_t)chunk * 64) * DD);

    const int dvec = tid & 63;          // float4 index within row
    const int rg = tid >> 6;            // row group 0..3
    float4 s = make_float4(0.f, 0.f, 0.f, 0.f);
    #pragma unroll 4
    for (int it = 0; it < 16; it++) {
        int row = it * 4 + rg;
        float4 v = src[(size_t)row * 64 + dvec];
        s.x += v.x; s.y += v.y; s.z += v.z; s.w += v.w;
        __nv_bfloat162 lo = __floats2bfloat162_rn(v.x, v.y);
        __nv_bfloat162 hi = __floats2bfloat162_rn(v.z, v.w);
        uint2 o;
        o.x = *reinterpret_cast<unsigned*>(&lo);
        o.y = *reinterpret_cast<unsigned*>(&hi);
        dst[(size_t)row * 64 + dvec] = o;
    }
    float4* mp = (float4*)&g_meanpart[((size_t)bx * 4 + rg) * DD];
    mp[dvec] = s;
}

// ---------------- kWqa: kW tiles + k1a tiles (one launch, 128 CTAs) -----------
// bid: b = bid>>3, s = bid&7. s<4: kW (tileM=s>>1, tileN=s&1).
// s>=4: k1a (mi=(s-4)>>1, tileN=(s-4)&1).
__global__ void __launch_bounds__(256, 2) kWqa() {
    extern __shared__ char sm[];
    uint32_t smb = smem_u32(sm);
    int tid = threadIdx.x;
    int b = blockIdx.x >> 3;
    int s = blockIdx.x & 7;

    ACC_DECL_ZERO(acc);
    if (s < 4) {
        int tileM = s >> 1, tileN = s & 1;
        gemm_mainloop(smb, g_ab + ((size_t)b * TT + (size_t)tileM * 128) * DD,
                      g_Ub + (size_t)tileN * 128 * DD, tid, acc);
        epi_store_bf16(acc, tid, g_Wt + (size_t)b * 256 * DD,
                       tileM * 128, tileN * 128, DD);
    } else {
        int mi = (s - 4) >> 1, tileN = (s - 4) & 1;
        gemm_mainloop(smb, g_qb + (size_t)(b * 16 + mi) * 128 * DD,
                      g_Ut + (size_t)tileN * 128 * DD, tid, acc);
        epi_store_bf16(acc, tid, g_qU, (b * 16 + mi) * 128, tileN * 128, DD);
    }
}

// ---------------- kCert: kG_sample + col-cert (one launch, 960 CTAs) ----------
// bid: b = bid/60, s = bid%60. s<32: kG (j=s>>1, tileN=s&1): row samples for
// all rows + exact col maxes 0..255. s>=32: col-cert (nj=2+(g>>1), mi=g&1).
__global__ void __launch_bounds__(256, 2) kCert() {
    extern __shared__ char sm[];
    uint32_t smb = smem_u32(sm);
    int tid = threadIdx.x;
    int b = blockIdx.x / 60;
    int s = blockIdx.x % 60;

    ACC_DECL_ZERO(acc);
    if (s < 32) {
        int j = s >> 1, tileN = s & 1;
        gemm_mainloop(smb, g_qb + (size_t)(b * 16 + j) * 128 * DD,
                      g_Wt + (size_t)b * 256 * DD + (size_t)tileN * 128 * DD, tid, acc);
        epi_max(acc, tid, (b * 16 + j) * 128, b * TT + tileN * 128);
    } else {
        int g = s - 32;
        int nj = 2 + (g >> 1), mi = g & 1;
        gemm_mainloop(smb, g_qU + ((size_t)b * TT + (size_t)mi * 128) * DD,
                      g_ab + ((size_t)b * TT + (size_t)nj * 128) * DD, tid, acc);
        epi_max(acc, tid, b * TT + mi * 128, b * TT + nj * 128);
    }
}

// ---------------- kCheckMean: cert check (vectorized) + mean stage-1 ----------
// bid<256: stage-1 reduce 1024 -> 256 partial vectors (16:1).
// bid in [256,288): check 8 elements/thread via uint4 x2.
__global__ void kCheckMean() {
    int bid = blockIdx.x;
    int tid = threadIdx.x;
    if (bid < 256) {
        float s = 0.0f;
        #pragma unroll
        for (int j = 0; j < 16; j++)
            s += g_meanpart[(size_t)(bid * 16 + j) * DD + tid];
        g_mean2[(size_t)bid * DD + tid] = s;
        return;
    }
    int base = ((bid - 256) * 256 + tid) * 8;   // 0..65528, 8-aligned
    const uint4* src = (base < BB * TT)
        ? (const uint4*)&g_rmax[base]
        : (const uint4*)&g_cmax[base - BB * TT];
    uint4 v0 = src[0], v1 = src[1];
    unsigned m = v0.x;
    m = min(m, v0.y); m = min(m, v0.z); m = min(m, v0.w);
    m = min(m, v1.x); m = min(m, v1.y); m = min(m, v1.z); m = min(m, v1.w);
    if (decf(m) < CERT_THRESH) atomicOr(&g_need_full, 1);
}

// ---------------- k_out: certified path -> means (stage 2) --------------------
__global__ void k_out_mean(float* __restrict__ out) {
    if (g_need_full) return;
    int i = blockIdx.x * 256 + threadIdx.x;   // 0..8191
    int which = i >> 12;
    int b = (i >> 8) & 15;
    int d = i & 255;
    int base = which * 128 + b * 8;
    float s = 0.0f;
    #pragma unroll
    for (int j = 0; j < 8; j++) s += g_mean2[(size_t)(base + j) * DD + d];
    out[i] = s * (1.0f / (float)TT);
}

// ---------------- gated fallback: complete qU (7 tiles per CTA) ---------------
__global__ void __launch_bounds__(256, 2) k1_qU_gated() {
    if (g_need_full == 0) return;
    extern __shared__ char sm[];
    uint32_t smb = smem_u32(sm);
    int tid = threadIdx.x;
    int tileN = blockIdx.x & 1;
    int group = blockIdx.x >> 1;   // 0..31
    for (int i = 0; i < 7; i++) {
        int y = group * 7 + i;     // 0..223
        int tileM = (y / 14) * 16 + 2 + (y % 14);
        ACC_DECL_ZERO(acc);
        gemm_mainloop(smb, g_qb + (size_t)tileM * 128 * DD,
                      g_Ut + (size_t)tileN * 128 * DD, tid, acc);
        epi_store_bf16(acc, tid, g_qU, tileM * 128, tileN * 128, DD);
        __syncthreads();
    }
}

// ---------------- gated fallback: remaining G tiles (7 per CTA) ----------------
__global__ void __launch_bounds__(256, 2) k2_gated() {
    if (g_need_full == 0) return;
    extern __shared__ char sm[];
    uint32_t smb = smem_u32(sm);
    int tid = threadIdx.x;
    int nj = blockIdx.x + 2;
    int yy = blockIdx.y;           // 0..1
    int b  = blockIdx.z;
    for (int i = 0; i < 7; i++) {
        int mi = 2 + yy * 7 + i;   // 2..15
        ACC_DECL_ZERO(acc);
        gemm_mainloop(smb, g_qU + ((size_t)b * TT + (size_t)mi * 128) * DD,
                      g_ab + ((size_t)b * TT + (size_t)nj * 128) * DD, tid, acc);
        epi_max(acc, tid, b * TT + mi * 128, b * TT + nj * 128);
        __syncthreads();
    }
}

// ---------------- fallback k3a: tanh + softmax over T -> weights --------------
__global__ void k3a_weights() {
    if (g_need_full == 0) return;
    __shared__ float red[256];
    int tid = threadIdx.x;
    int which = blockIdx.x >> 4;
    int b = blockIdx.x & 15;
    const unsigned* src = (which ? g_cmax : g_rmax) + b * TT;
    float* dst = g_wts + (size_t)(which * BB + b) * TT;

    float tv[8];
    #pragma unroll
    for (int i = 0; i < 8; i++) tv[i] = tanhf(decf(src[i * 256 + tid]));

    float lm = tv[0];
    #pragma unroll
    for (int i = 1; i < 8; i++) lm = fmaxf(lm, tv[i]);
    red[tid] = lm;
    __syncthreads();
    for (int s = 128; s > 0; s >>= 1) {
        if (tid < s) red[tid] = fmaxf(red[tid], red[tid + s]);
        __syncthreads();
    }
    float mx = red[0];
    __syncthreads();

    float ls = 0.0f;
    #pragma unroll
    for (int i = 0; i < 8; i++) ls += expf(tv[i] - mx);
    red[tid] = ls;
    __syncthreads();
    for (int s = 128; s > 0; s >>= 1) {
        if (tid < s) red[tid] += red[tid + s];
        __syncthreads();
    }
    float inv = 1.0f / red[0];

    #pragma unroll
    for (int i = 0; i < 8; i++) dst[i * 256 + tid] = expf(tv[i] - mx) * inv;
}

// ---------------- fallback k3b: weighted pooling partials ----------------------
__global__ void k3b_pool(const float* __restrict__ q, const float* __restrict__ a) {
    if (g_need_full == 0) return;
    __shared__ float ws[256];
    int tid = threadIdx.x;
    int slice = blockIdx.x & 7;
    int b     = (blockIdx.x >> 3) & 15;
    int which = blockIdx.x >> 7;

    ws[tid] = g_wts[(size_t)(which * BB + b) * TT + slice * 256 + tid];
    __syncthreads();

    const float* src = which ? a : q;
    const float* base = src + ((size_t)b * TT + (size_t)slice * 256) * DD + tid;
    float acc = 0.0f;
    #pragma unroll 8
    for (int t = 0; t < 256; t++) acc += ws[t] * base[(size_t)t * DD];
    g_part[(size_t)blockIdx.x * 256 + tid] = acc;
}

// ---------------- fallback k3c: reduce partials -> output ----------------------
__global__ void k3c_reduce(float* __restrict__ out) {
    if (g_need_full == 0) return;
    int i = blockIdx.x * 256 + threadIdx.x;
    int which = i >> 12;
    int b = (i >> 8) & 15;
    int d = i & 255;
    size_t pb = ((size_t)(which * BB + b) * 8) * 256 + d;
    float s = 0.0f;
    #pragma unroll
    for (int k = 0; k < 8; k++) s += g_part[pb + (size_t)k * 256];
    out[i] = s;
}

// ---------------- launch ------------------------------------------------------
extern "C" void kernel_launch(void* const* d_in, const int* in_sizes, int n_in,
                              void* d_out, int out_size) {
    int ui = 2;
    for (int i = 0; i < n_in; i++)
        if (in_sizes[i] == DD * DD) ui = i;
    const float* ptrs[3];
    int k = 0;
    for (int i = 0; i < n_in && k < 3; i++)
        if (i != ui) ptrs[k++] = (const float*)d_in[i];
    const float* q = ptrs[0];
    const float* a = ptrs[1];
    const float* U = (const float*)d_in[ui];
    float* out = (float*)d_out;

    static int init_done = 0;
    if (!init_done) {
        cudaFuncSetAttribute(kWqa,        cudaFuncAttributeMaxDynamicSharedMemorySize, GEMM_SMEM);
        cudaFuncSetAttribute(kCert,       cudaFuncAttributeMaxDynamicSharedMemorySize, GEMM_SMEM);
        cudaFuncSetAttribute(k1_qU_gated, cudaFuncAttributeMaxDynamicSharedMemorySize, GEMM_SMEM);
        cudaFuncSetAttribute(k2_gated,    cudaFuncAttributeMaxDynamicSharedMemorySize, GEMM_SMEM);
        init_done = 1;
    }

    // converts + mean partials + U^T/U + zero maxes (no-smem, high occupancy)
    k0_convert<<<1096, 256>>>(q, a, U);
    // Wt tiles + qU rows {0,1}/batch (merged, 128 CTAs)
    kWqa<<<128, 256, GEMM_SMEM>>>();
    // kG_sample + col-cert (merged, 960 CTAs)
    kCert<<<960, 256, GEMM_SMEM>>>();
    // cert check (vectorized) + mean stage-1, then certified output
    kCheckMean<<<288, 256>>>();
    k_out_mean<<<32, 256>>>(out);
    // fallback (self-disabled when certified; loop-tiled to shrink no-op dispatch)
    k1_qU_gated<<<64, 256, GEMM_SMEM>>>();
    k2_gated<<<dim3(14, 2, 16), 256, GEMM_SMEM>>>();
    k3a_weights<<<32, 256>>>();
    k3b_pool<<<256, 256>>>(q, a);
    k3c_reduce<<<32, 256>>>(out);
    (void)out_size;
}

// round 14
// speedup vs baseline: 1.4329x; 1.0206x over previous
#include <cuda_runtime.h>
#include <cuda_bf16.h>
#include <stdint.h>
#include <math.h>

#define BB 16
#define TT 2048
#define DD 256

// Certification threshold: computed (bf16-mma) lower bound on a row/col max.
// tanh saturates to exactly 1.0f for x >= ~9.0; bf16 pipeline error << 0.6,
// so a computed bound >= 9.6 certifies saturation of that row/col max.
#define CERT_THRESH 9.6f

// ---------------- scratch (static __device__ arrays; no runtime allocation) ----
__device__ __nv_bfloat16 g_qb[BB*TT*DD];    // q in bf16
__device__ __nv_bfloat16 g_ab[BB*TT*DD];    // a in bf16
__device__ __nv_bfloat16 g_Ut[DD*DD];       // U^T in bf16 (Ut[e][d] = U[d][e])
__device__ __nv_bfloat16 g_Ub[DD*DD];       // U in bf16 (row-major)
__device__ __nv_bfloat16 g_qU[BB*TT*DD];    // qU in bf16 (rows {0,1}/batch + gated rest)
__device__ __nv_bfloat16 g_Wt[BB*256*DD];   // Wt[b][j][d] = sum_e a[b,j,e]*U[d,e]
__device__ unsigned      g_rmax[BB*TT];     // encoded float max per q-row
__device__ unsigned      g_cmax[BB*TT];     // encoded float max per a-col
__device__ float         g_meanpart[1024*4*DD]; // per-(chunk,rowgroup) mean partials
__device__ float         g_mean2[256*DD];   // stage-1 reduced mean partials
__device__ int           g_need_full;       // 0 = certified (means exact)

// ---------------- helpers ----------------
__device__ __forceinline__ uint32_t smem_u32(const void* p) {
    uint32_t r;
    asm("{ .reg .u64 t; cvta.to.shared.u64 t, %1; cvt.u32.u64 %0, t; }"
        : "=r"(r) : "l"(p));
    return r;
}

__device__ __forceinline__ void cpasync16(uint32_t s, const void* g) {
    asm volatile("cp.async.cg.shared.global [%0], [%1], 16;" :: "r"(s), "l"(g) : "memory");
}
#define CP_COMMIT() asm volatile("cp.async.commit_group;" ::: "memory")
#define CP_WAIT0()  asm volatile("cp.async.wait_group 0;" ::: "memory")

__device__ __forceinline__ void ldmx4(uint32_t addr, uint32_t& r0, uint32_t& r1,
                                      uint32_t& r2, uint32_t& r3) {
    asm volatile("ldmatrix.sync.aligned.m8n8.x4.shared.b16 {%0,%1,%2,%3}, [%4];"
                 : "=r"(r0), "=r"(r1), "=r"(r2), "=r"(r3) : "r"(addr));
}

__device__ __forceinline__ void mma16816(float* c, uint32_t a0, uint32_t a1,
                                         uint32_t a2, uint32_t a3,
                                         uint32_t b0, uint32_t b1) {
    asm volatile(
        "mma.sync.aligned.m16n8k16.row.col.f32.bf16.bf16.f32 "
        "{%0,%1,%2,%3}, {%4,%5,%6,%7}, {%8,%9}, {%0,%1,%2,%3};"
        : "+f"(c[0]), "+f"(c[1]), "+f"(c[2]), "+f"(c[3])
        : "r"(a0), "r"(a1), "r"(a2), "r"(a3), "r"(b0), "r"(b1));
}

__device__ __forceinline__ unsigned encf(float f) {
    unsigned u = __float_as_uint(f);
    return (u & 0x80000000u) ? ~u : (u | 0x80000000u);
}
__device__ __forceinline__ float decf(unsigned e) {
    unsigned u = (e & 0x80000000u) ? (e & 0x7FFFFFFFu) : ~e;
    return __uint_as_float(u);
}

// ---------------- GEMM core: C[128x128] = A[128x256] * B[128x256]^T -----------
#define GEMM_SMEM 65536

__device__ __forceinline__ void load_chunk(uint32_t smb, int buf,
                                           const __nv_bfloat16* __restrict__ A,
                                           const __nv_bfloat16* __restrict__ Bm,
                                           int ck, int tid) {
    const __nv_bfloat16* Ac = A + ck * 64;
    const __nv_bfloat16* Bc = Bm + ck * 64;
    #pragma unroll
    for (int i = 0; i < 4; i++) {
        int v = tid + i * 256;
        int row = v >> 3, kv = v & 7;
        uint32_t o = (uint32_t)row * 128u + (uint32_t)kv * 16u;
        o ^= (o >> 3) & 0x70u;
        const size_t goff = (size_t)row * DD + (size_t)kv * 8;
        cpasync16(smb + buf * 16384 + o, Ac + goff);
        cpasync16(smb + 32768 + buf * 16384 + o, Bc + goff);
    }
}

// Single-sync double-buffered pipeline:
//   wait(chunk ck) -> syncthreads -> prefetch ck+1 -> compute ck
__device__ __forceinline__ void gemm_mainloop(uint32_t smb, const __nv_bfloat16* A,
                                              const __nv_bfloat16* Bm, int tid,
                                              float acc[4][4][4]) {
    const int lid = tid & 31, w = tid >> 5;
    const int wm = (w >> 2) * 64, wn = (w & 3) * 32;
    const int lrow = lid & 15;
    const uint32_t khalf = (uint32_t)(lid >> 4) * 16u;

    load_chunk(smb, 0, A, Bm, 0, tid);
    CP_COMMIT();

    #pragma unroll
    for (int ck = 0; ck < 4; ck++) {
        CP_WAIT0();
        __syncthreads();
        if (ck + 1 < 4) {
            load_chunk(smb, (ck + 1) & 1, A, Bm, ck + 1, tid);
            CP_COMMIT();
        }

        const uint32_t abase = smb + (ck & 1) * 16384;
        const uint32_t bbase = smb + 32768 + (ck & 1) * 16384;

        #pragma unroll
        for (int kk = 0; kk < 4; kk++) {
            const uint32_t koff = (uint32_t)kk * 32u + khalf;
            uint32_t a[4][4];
            #pragma unroll
            for (int mt = 0; mt < 4; mt++) {
                uint32_t o = (uint32_t)(wm + mt * 16 + lrow) * 128u + koff;
                o ^= (o >> 3) & 0x70u;
                ldmx4(abase + o, a[mt][0], a[mt][1], a[mt][2], a[mt][3]);
            }
            uint32_t b[4][2];
            #pragma unroll
            for (int np = 0; np < 2; np++) {
                uint32_t o = (uint32_t)(wn + np * 16 + lrow) * 128u + koff;
                o ^= (o >> 3) & 0x70u;
                uint32_t r0, r1, r2, r3;
                ldmx4(bbase + o, r0, r1, r2, r3);
                b[np * 2 + 0][0] = r0; b[np * 2 + 0][1] = r2;
                b[np * 2 + 1][0] = r1; b[np * 2 + 1][1] = r3;
            }
            #pragma unroll
            for (int mt = 0; mt < 4; mt++)
                #pragma unroll
                for (int nt = 0; nt < 4; nt++)
                    mma16816(acc[mt][nt], a[mt][0], a[mt][1], a[mt][2], a[mt][3],
                             b[nt][0], b[nt][1]);
        }
    }
}

// shared epilogues ------------------------------------------------------------
__device__ __forceinline__ void epi_store_bf16(const float acc[4][4][4], int tid,
                                               __nv_bfloat16* dstbase, int rowOff,
                                               int colOff, int rowStride) {
    const int lid = tid & 31, w = tid >> 5;
    const int wm = (w >> 2) * 64, wn = (w & 3) * 32;
    const int g = lid >> 2, tg = lid & 3;
    #pragma unroll
    for (int mt = 0; mt < 4; mt++) {
        int row0 = rowOff + wm + mt * 16 + g;
        #pragma unroll
        for (int nt = 0; nt < 4; nt++) {
            int col = colOff + wn + nt * 8 + 2 * tg;
            __nv_bfloat162 p0 = __floats2bfloat162_rn(acc[mt][nt][0], acc[mt][nt][1]);
            __nv_bfloat162 p1 = __floats2bfloat162_rn(acc[mt][nt][2], acc[mt][nt][3]);
            *reinterpret_cast<unsigned*>(dstbase + (size_t)row0 * rowStride + col) =
                *reinterpret_cast<unsigned*>(&p0);
            *reinterpret_cast<unsigned*>(dstbase + (size_t)(row0 + 8) * rowStride + col) =
                *reinterpret_cast<unsigned*>(&p1);
        }
    }
}

__device__ __forceinline__ void epi_max(const float acc[4][4][4], int tid,
                                        int rowBase, int colBase) {
    const int lid = tid & 31, w = tid >> 5;
    const int wm = (w >> 2) * 64, wn = (w & 3) * 32;
    const int g = lid >> 2, tg = lid & 3;
    const int rb = rowBase + wm;
    const int cb = colBase + wn;

    #pragma unroll
    for (int mt = 0; mt < 4; mt++) {
        float r0 = -3.0e38f, r1 = -3.0e38f;
        #pragma unroll
        for (int nt = 0; nt < 4; nt++) {
            r0 = fmaxf(r0, fmaxf(acc[mt][nt][0], acc[mt][nt][1]));
            r1 = fmaxf(r1, fmaxf(acc[mt][nt][2], acc[mt][nt][3]));
        }
        r0 = fmaxf(r0, __shfl_xor_sync(0xffffffffu, r0, 1));
        r0 = fmaxf(r0, __shfl_xor_sync(0xffffffffu, r0, 2));
        r1 = fmaxf(r1, __shfl_xor_sync(0xffffffffu, r1, 1));
        r1 = fmaxf(r1, __shfl_xor_sync(0xffffffffu, r1, 2));
        if (tg == 0) {
            atomicMax(&g_rmax[rb + mt * 16 + g], encf(r0));
            atomicMax(&g_rmax[rb + mt * 16 + g + 8], encf(r1));
        }
    }
    #pragma unroll
    for (int nt = 0; nt < 4; nt++) {
        float c0 = -3.0e38f, c1 = -3.0e38f;
        #pragma unroll
        for (int mt = 0; mt < 4; mt++) {
            c0 = fmaxf(c0, fmaxf(acc[mt][nt][0], acc[mt][nt][2]));
            c1 = fmaxf(c1, fmaxf(acc[mt][nt][1], acc[mt][nt][3]));
        }
        #pragma unroll
        for (int s = 4; s < 32; s <<= 1) {
            c0 = fmaxf(c0, __shfl_xor_sync(0xffffffffu, c0, s));
            c1 = fmaxf(c1, __shfl_xor_sync(0xffffffffu, c1, s));
        }
        if (g == 0) {
            atomicMax(&g_cmax[cb + nt * 8 + 2 * tg], encf(c0));
            atomicMax(&g_cmax[cb + nt * 8 + 2 * tg + 1], encf(c1));
        }
    }
}

#define ACC_DECL_ZERO(acc) \
    float acc[4][4][4]; \
    _Pragma("unroll") for (int _i = 0; _i < 4; _i++) \
    _Pragma("unroll") for (int _j = 0; _j < 4; _j++) \
    _Pragma("unroll") for (int _r = 0; _r < 4; _r++) acc[_i][_j][_r] = 0.0f;

// ---------------- k0: convert fp32->bf16 + mean partials + aux ---------------
// bx < 1024: convert 64-row chunks (q: bx<512, a: 512..1023). No smem ->
// high occupancy, BW-bound.
// bx in [1024,1088): 64 zero blocks; [1088,1096): 8 U blocks (4 Ut + 4 Ub).
__global__ void __launch_bounds__(256) k0_convert(const float* __restrict__ q,
                                                  const float* __restrict__ a,
                                                  const float* __restrict__ U) {
    int bx = blockIdx.x;
    int tid = threadIdx.x;

    if (bx >= 1024) {
        int bz = bx - 1024;
        if (bz < 64) {
            int i0 = (bz * 256 + tid) * 2;
            g_rmax[i0] = 0u; g_rmax[i0 + 1] = 0u;
            g_cmax[i0] = 0u; g_cmax[i0 + 1] = 0u;
            if (bz == 0 && tid == 0) g_need_full = 0;
        } else if (bz < 68) {
            int blk = bz - 64;   // Ut
            #pragma unroll 4
            for (int it = 0; it < 64; it++) {
                int i = blk * 16384 + it * 256 + tid;
                int d = i >> 8, e = i & 255;
                g_Ut[e * DD + d] = __float2bfloat16(U[i]);
            }
        } else {
            int blk = bz - 68;   // Ub (straight)
            #pragma unroll 4
            for (int it = 0; it < 64; it++) {
                int i = blk * 16384 + it * 256 + tid;
                g_Ub[i] = __float2bfloat16(U[i]);
            }
        }
        return;
    }

    int tensor = bx >> 9;
    int local = bx & 511;
    int b = local >> 5;
    int chunk = local & 31;   // 64-row chunk
    const float4* src = (const float4*)((tensor ? a : q) +
                        ((size_t)b * TT + (size_t)chunk * 64) * DD);
    uint2* dst = (uint2*)((tensor ? g_ab : g_qb) +
                 ((size_t)b * TT + (size_t)chunk * 64) * DD);

    const int dvec = tid & 63;          // float4 index within row
    const int rg = tid >> 6;            // row group 0..3
    float4 s = make_float4(0.f, 0.f, 0.f, 0.f);
    #pragma unroll 4
    for (int it = 0; it < 16; it++) {
        int row = it * 4 + rg;
        float4 v = src[(size_t)row * 64 + dvec];
        s.x += v.x; s.y += v.y; s.z += v.z; s.w += v.w;
        __nv_bfloat162 lo = __floats2bfloat162_rn(v.x, v.y);
        __nv_bfloat162 hi = __floats2bfloat162_rn(v.z, v.w);
        uint2 o;
        o.x = *reinterpret_cast<unsigned*>(&lo);
        o.y = *reinterpret_cast<unsigned*>(&hi);
        dst[(size_t)row * 64 + dvec] = o;
    }
    float4* mp = (float4*)&g_meanpart[((size_t)bx * 4 + rg) * DD];
    mp[dvec] = s;
}

// ---------------- kWqa: kW + k1a GEMM tiles + mean stage-1 (one launch) -------
// bid<128: b = bid>>3, s = bid&7. s<4: kW tile; s>=4: k1a tile.
// bid in [128,384): mean stage-1 — sum 16 meanpart slot-vectors -> g_mean2.
// (mean CTAs read only 4 MB total; 2-CTA/SM smem cap cannot BW-starve them,
//  and they fill the SM slots the 128 GEMM CTAs leave idle.)
__global__ void __launch_bounds__(256, 2) kWqa() {
    extern __shared__ char sm[];
    int tid = threadIdx.x;
    int bid = blockIdx.x;

    if (bid >= 128) {
        int v = bid - 128;   // 0..255
        float s = 0.0f;
        #pragma unroll
        for (int j = 0; j < 16; j++)
            s += g_meanpart[(size_t)(v * 16 + j) * DD + tid];
        g_mean2[(size_t)v * DD + tid] = s;
        return;
    }

    uint32_t smb = smem_u32(sm);
    int b = bid >> 3;
    int s = bid & 7;

    ACC_DECL_ZERO(acc);
    if (s < 4) {
        int tileM = s >> 1, tileN = s & 1;
        gemm_mainloop(smb, g_ab + ((size_t)b * TT + (size_t)tileM * 128) * DD,
                      g_Ub + (size_t)tileN * 128 * DD, tid, acc);
        epi_store_bf16(acc, tid, g_Wt + (size_t)b * 256 * DD,
                       tileM * 128, tileN * 128, DD);
    } else {
        int mi = (s - 4) >> 1, tileN = (s - 4) & 1;
        gemm_mainloop(smb, g_qb + (size_t)(b * 16 + mi) * 128 * DD,
                      g_Ut + (size_t)tileN * 128 * DD, tid, acc);
        epi_store_bf16(acc, tid, g_qU, (b * 16 + mi) * 128, tileN * 128, DD);
    }
}

// ---------------- kCert: kG_sample + col-cert (one launch, 960 CTAs) ----------
// bid: b = bid/60, s = bid%60. s<32: kG (j=s>>1, tileN=s&1): row samples for
// all rows + exact col maxes 0..255. s>=32: col-cert (nj=2+(g>>1), mi=g&1).
__global__ void __launch_bounds__(256, 2) kCert() {
    extern __shared__ char sm[];
    uint32_t smb = smem_u32(sm);
    int tid = threadIdx.x;
    int b = blockIdx.x / 60;
    int s = blockIdx.x % 60;

    ACC_DECL_ZERO(acc);
    if (s < 32) {
        int j = s >> 1, tileN = s & 1;
        gemm_mainloop(smb, g_qb + (size_t)(b * 16 + j) * 128 * DD,
                      g_Wt + (size_t)b * 256 * DD + (size_t)tileN * 128 * DD, tid, acc);
        epi_max(acc, tid, (b * 16 + j) * 128, b * TT + tileN * 128);
    } else {
        int g = s - 32;
        int nj = 2 + (g >> 1), mi = g & 1;
        gemm_mainloop(smb, g_qU + ((size_t)b * TT + (size_t)mi * 128) * DD,
                      g_ab + ((size_t)b * TT + (size_t)nj * 128) * DD, tid, acc);
        epi_max(acc, tid, b * TT + mi * 128, b * TT + nj * 128);
    }
}

// ---------------- kCheck: certify saturation (32 CTAs, uint4 x2 / thread) -----
__global__ void kCheck() {
    int base = (blockIdx.x * 256 + threadIdx.x) * 8;   // 0..65528, 8-aligned
    const uint4* src = (base < BB * TT)
        ? (const uint4*)&g_rmax[base]
        : (const uint4*)&g_cmax[base - BB * TT];
    uint4 v0 = src[0], v1 = src[1];
    unsigned m = v0.x;
    m = min(m, v0.y); m = min(m, v0.z); m = min(m, v0.w);
    m = min(m, v1.x); m = min(m, v1.y); m = min(m, v1.z); m = min(m, v1.w);
    if (decf(m) < CERT_THRESH) atomicOr(&g_need_full, 1);
}

// ---------------- gated fallback: complete qU (7 tiles per CTA) ---------------
__global__ void __launch_bounds__(256, 2) k1_qU_gated() {
    if (g_need_full == 0) return;
    extern __shared__ char sm[];
    uint32_t smb = smem_u32(sm);
    int tid = threadIdx.x;
    int tileN = blockIdx.x & 1;
    int group = blockIdx.x >> 1;   // 0..31
    for (int i = 0; i < 7; i++) {
        int y = group * 7 + i;     // 0..223
        int tileM = (y / 14) * 16 + 2 + (y % 14);
        ACC_DECL_ZERO(acc);
        gemm_mainloop(smb, g_qb + (size_t)tileM * 128 * DD,
                      g_Ut + (size_t)tileN * 128 * DD, tid, acc);
        epi_store_bf16(acc, tid, g_qU, tileM * 128, tileN * 128, DD);
        __syncthreads();
    }
}

// ---------------- gated fallback: remaining G tiles (7 per CTA) ----------------
__global__ void __launch_bounds__(256, 2) k2_gated() {
    if (g_need_full == 0) return;
    extern __shared__ char sm[];
    uint32_t smb = smem_u32(sm);
    int tid = threadIdx.x;
    int nj = blockIdx.x + 2;
    int yy = blockIdx.y;           // 0..1
    int b  = blockIdx.z;
    for (int i = 0; i < 7; i++) {
        int mi = 2 + yy * 7 + i;   // 2..15
        ACC_DECL_ZERO(acc);
        gemm_mainloop(smb, g_qU + ((size_t)b * TT + (size_t)mi * 128) * DD,
                      g_ab + ((size_t)b * TT + (size_t)nj * 128) * DD, tid, acc);
        epi_max(acc, tid, b * TT + mi * 128, b * TT + nj * 128);
        __syncthreads();
    }
}

// ---------------- kOutFinal: certified means OR fallback softmax+pool ---------
// grid 32: which = bid>>4, b = bid&15, d = tid.
__global__ void kOutFinal(const float* __restrict__ q, const float* __restrict__ a,
                          float* __restrict__ out) {
    __shared__ float ws[TT];
    __shared__ float red[256];
    int tid = threadIdx.x;
    int which = blockIdx.x >> 4;
    int b = blockIdx.x & 15;

    if (g_need_full == 0) {
        // certified: mean stage-2 (8 contiguous g_mean2 slot-vectors)
        int base = which * 128 + b * 8;
        float s = 0.0f;
        #pragma unroll
        for (int j = 0; j < 8; j++) s += g_mean2[(size_t)(base + j) * DD + tid];
        out[which * BB * DD + b * DD + tid] = s * (1.0f / (float)TT);
        return;
    }

    // fallback: softmax over tanh'd maxes, then weighted pooling
    const unsigned* src = (which ? g_cmax : g_rmax) + b * TT;
    float tv[8];
    #pragma unroll
    for (int i = 0; i < 8; i++) tv[i] = tanhf(decf(src[i * 256 + tid]));

    float lm = tv[0];
    #pragma unroll
    for (int i = 1; i < 8; i++) lm = fmaxf(lm, tv[i]);
    red[tid] = lm;
    __syncthreads();
    for (int s = 128; s > 0; s >>= 1) {
        if (tid < s) red[tid] = fmaxf(red[tid], red[tid + s]);
        __syncthreads();
    }
    float mx = red[0];
    __syncthreads();

    float ls = 0.0f;
    #pragma unroll
    for (int i = 0; i < 8; i++) ls += expf(tv[i] - mx);
    red[tid] = ls;
    __syncthreads();
    for (int s = 128; s > 0; s >>= 1) {
        if (tid < s) red[tid] += red[tid + s];
        __syncthreads();
    }
    float inv = 1.0f / red[0];
    __syncthreads();

    #pragma unroll
    for (int i = 0; i < 8; i++) ws[i * 256 + tid] = expf(tv[i] - mx) * inv;
    __syncthreads();

    const float* basep = (which ? a : q) + (size_t)b * TT * DD + tid;
    float acc = 0.0f;
    for (int t = 0; t < TT; t++) acc += ws[t] * basep[(size_t)t * DD];
    out[which * BB * DD + b * DD + tid] = acc;
}

// ---------------- launch ------------------------------------------------------
extern "C" void kernel_launch(void* const* d_in, const int* in_sizes, int n_in,
                              void* d_out, int out_size) {
    int ui = 2;
    for (int i = 0; i < n_in; i++)
        if (in_sizes[i] == DD * DD) ui = i;
    const float* ptrs[3];
    int k = 0;
    for (int i = 0; i < n_in && k < 3; i++)
        if (i != ui) ptrs[k++] = (const float*)d_in[i];
    const float* q = ptrs[0];
    const float* a = ptrs[1];
    const float* U = (const float*)d_in[ui];
    float* out = (float*)d_out;

    static int init_done = 0;
    if (!init_done) {
        cudaFuncSetAttribute(kWqa,        cudaFuncAttributeMaxDynamicSharedMemorySize, GEMM_SMEM);
        cudaFuncSetAttribute(kCert,       cudaFuncAttributeMaxDynamicSharedMemorySize, GEMM_SMEM);
        cudaFuncSetAttribute(k1_qU_gated, cudaFuncAttributeMaxDynamicSharedMemorySize, GEMM_SMEM);
        cudaFuncSetAttribute(k2_gated,    cudaFuncAttributeMaxDynamicSharedMemorySize, GEMM_SMEM);
        init_done = 1;
    }

    // converts + mean partials + U^T/U + zero maxes (no-smem, high occupancy)
    k0_convert<<<1096, 256>>>(q, a, U);
    // Wt tiles + qU rows {0,1}/batch + mean stage-1 filling idle SMs
    kWqa<<<384, 256, GEMM_SMEM>>>();
    // kG_sample + col-cert (merged, 960 CTAs)
    kCert<<<960, 256, GEMM_SMEM>>>();
    // certification check (32 CTAs, vectorized)
    kCheck<<<32, 256>>>();
    // fallback GEMMs (self-disabled when certified; loop-tiled dispatch)
    k1_qU_gated<<<64, 256, GEMM_SMEM>>>();
    k2_gated<<<dim3(14, 2, 16), 256, GEMM_SMEM>>>();
    // final output: certified means OR fallback softmax+pool
    kOutFinal<<<32, 256>>>(q, a, out);
    (void)out_size;
}

// round 15
// speedup vs baseline: 1.4407x; 1.0055x over previous
#include <cuda_runtime.h>
#include <cuda_bf16.h>
#include <stdint.h>
#include <math.h>

#define BB 16
#define TT 2048
#define DD 256

// Certification threshold: computed (bf16-mma) lower bound on a row/col max.
// tanh saturates to exactly 1.0f for x >= ~9.0; bf16 pipeline error << 0.6,
// so a computed bound >= 9.6 certifies saturation of that row/col max.
#define CERT_THRESH 9.6f

// ---------------- scratch (static __device__ arrays; no runtime allocation) ----
__device__ __nv_bfloat16 g_qb[BB*TT*DD];    // q in bf16
__device__ __nv_bfloat16 g_ab[BB*TT*DD];    // a in bf16
__device__ __nv_bfloat16 g_Ut[DD*DD];       // U^T in bf16 (Ut[e][d] = U[d][e])
__device__ __nv_bfloat16 g_Ub[DD*DD];       // U in bf16 (row-major)
__device__ __nv_bfloat16 g_qU[BB*TT*DD];    // qU in bf16 (rows {0,1}/batch + gated rest)
__device__ __nv_bfloat16 g_Wt[BB*256*DD];   // Wt[b][j][d] = sum_e a[b,j,e]*U[d,e]
__device__ unsigned      g_rmax[BB*TT];     // encoded float max per q-row
__device__ unsigned      g_cmax[BB*TT];     // encoded float max per a-col
__device__ float         g_meanpart[1024*4*DD]; // per-(chunk,rowgroup) mean partials
__device__ float         g_mean2[256*DD];   // stage-1 reduced mean partials
__device__ int           g_need_full;       // 0 = certified (means exact)

// ---------------- helpers ----------------
__device__ __forceinline__ uint32_t smem_u32(const void* p) {
    uint32_t r;
    asm("{ .reg .u64 t; cvta.to.shared.u64 t, %1; cvt.u32.u64 %0, t; }"
        : "=r"(r) : "l"(p));
    return r;
}

__device__ __forceinline__ void cpasync16(uint32_t s, const void* g) {
    asm volatile("cp.async.cg.shared.global [%0], [%1], 16;" :: "r"(s), "l"(g) : "memory");
}
#define CP_COMMIT() asm volatile("cp.async.commit_group;" ::: "memory")
#define CP_WAIT0()  asm volatile("cp.async.wait_group 0;" ::: "memory")

__device__ __forceinline__ void ldmx4(uint32_t addr, uint32_t& r0, uint32_t& r1,
                                      uint32_t& r2, uint32_t& r3) {
    asm volatile("ldmatrix.sync.aligned.m8n8.x4.shared.b16 {%0,%1,%2,%3}, [%4];"
                 : "=r"(r0), "=r"(r1), "=r"(r2), "=r"(r3) : "r"(addr));
}

__device__ __forceinline__ void mma16816(float* c, uint32_t a0, uint32_t a1,
                                         uint32_t a2, uint32_t a3,
                                         uint32_t b0, uint32_t b1) {
    asm volatile(
        "mma.sync.aligned.m16n8k16.row.col.f32.bf16.bf16.f32 "
        "{%0,%1,%2,%3}, {%4,%5,%6,%7}, {%8,%9}, {%0,%1,%2,%3};"
        : "+f"(c[0]), "+f"(c[1]), "+f"(c[2]), "+f"(c[3])
        : "r"(a0), "r"(a1), "r"(a2), "r"(a3), "r"(b0), "r"(b1));
}

__device__ __forceinline__ unsigned encf(float f) {
    unsigned u = __float_as_uint(f);
    return (u & 0x80000000u) ? ~u : (u | 0x80000000u);
}
__device__ __forceinline__ float decf(unsigned e) {
    unsigned u = (e & 0x80000000u) ? (e & 0x7FFFFFFFu) : ~e;
    return __uint_as_float(u);
}

// ---------------- GEMM core: C[128x128] = A[128x256] * B[128x256]^T -----------
#define GEMM_SMEM 65536

// Swizzle identity used throughout: for o = row*128 + k16 with k16 <= 112,
//   o ^ ((o>>3)&0x70) == row*128 + (k16 ^ ((row&7)*16))
// (low 7 bits of o are exactly k16; the xor operand is (row&7)*16; no carries.)
__device__ __forceinline__ void load_chunk(uint32_t smb, int buf,
                                           const __nv_bfloat16* __restrict__ A,
                                           const __nv_bfloat16* __restrict__ Bm,
                                           int ck, int tid) {
    const __nv_bfloat16* Ac = A + ck * 64;
    const __nv_bfloat16* Bc = Bm + ck * 64;
    #pragma unroll
    for (int i = 0; i < 4; i++) {
        int v = tid + i * 256;
        int row = v >> 3, kv = v & 7;
        uint32_t o = (uint32_t)row * 128u + (uint32_t)((kv ^ (row & 7)) * 16);
        const size_t goff = (size_t)row * DD + (size_t)kv * 8;
        cpasync16(smb + buf * 16384 + o, Ac + goff);
        cpasync16(smb + 32768 + buf * 16384 + o, Bc + goff);
    }
}

// Single-sync double-buffered pipeline:
//   wait(chunk ck) -> syncthreads -> prefetch ck+1 -> compute ck
// Addresses hoisted: per-fragment row byte-offsets are loop-invariant; the
// per-kk swizzled k offset (kswz) is ONE xor shared by all 6 ldmatrix ops.
__device__ __forceinline__ void gemm_mainloop(uint32_t smb, const __nv_bfloat16* A,
                                              const __nv_bfloat16* Bm, int tid,
                                              float acc[4][4][4]) {
    const int lid = tid & 31, w = tid >> 5;
    const int wm = (w >> 2) * 64, wn = (w & 3) * 32;
    const int lrow = lid & 15;
    const uint32_t khalf = (uint32_t)(lid >> 4) * 16u;
    const uint32_t rxor = (uint32_t)(lrow & 7) * 16u;

    uint32_t arow[4], brow[2];
    #pragma unroll
    for (int mt = 0; mt < 4; mt++) arow[mt] = (uint32_t)(wm + mt * 16 + lrow) * 128u;
    #pragma unroll
    for (int np = 0; np < 2; np++) brow[np] = (uint32_t)(wn + np * 16 + lrow) * 128u;

    load_chunk(smb, 0, A, Bm, 0, tid);
    CP_COMMIT();

    #pragma unroll
    for (int ck = 0; ck < 4; ck++) {
        CP_WAIT0();
        __syncthreads();
        if (ck + 1 < 4) {
            load_chunk(smb, (ck + 1) & 1, A, Bm, ck + 1, tid);
            CP_COMMIT();
        }

        const uint32_t abase = smb + (ck & 1) * 16384;
        const uint32_t bbase = smb + 32768 + (ck & 1) * 16384;

        #pragma unroll
        for (int kk = 0; kk < 4; kk++) {
            const uint32_t kswz = ((uint32_t)kk * 32u + khalf) ^ rxor;
            uint32_t a[4][4];
            #pragma unroll
            for (int mt = 0; mt < 4; mt++)
                ldmx4(abase + arow[mt] + kswz, a[mt][0], a[mt][1], a[mt][2], a[mt][3]);
            uint32_t b[4][2];
            #pragma unroll
            for (int np = 0; np < 2; np++) {
                uint32_t r0, r1, r2, r3;
                ldmx4(bbase + brow[np] + kswz, r0, r1, r2, r3);
                b[np * 2 + 0][0] = r0; b[np * 2 + 0][1] = r2;
                b[np * 2 + 1][0] = r1; b[np * 2 + 1][1] = r3;
            }
            #pragma unroll
            for (int mt = 0; mt < 4; mt++)
                #pragma unroll
                for (int nt = 0; nt < 4; nt++)
                    mma16816(acc[mt][nt], a[mt][0], a[mt][1], a[mt][2], a[mt][3],
                             b[nt][0], b[nt][1]);
        }
    }
}

// shared epilogues ------------------------------------------------------------
__device__ __forceinline__ void epi_store_bf16(const float acc[4][4][4], int tid,
                                               __nv_bfloat16* dstbase, int rowOff,
                                               int colOff, int rowStride) {
    const int lid = tid & 31, w = tid >> 5;
    const int wm = (w >> 2) * 64, wn = (w & 3) * 32;
    const int g = lid >> 2, tg = lid & 3;
    #pragma unroll
    for (int mt = 0; mt < 4; mt++) {
        int row0 = rowOff + wm + mt * 16 + g;
        #pragma unroll
        for (int nt = 0; nt < 4; nt++) {
            int col = colOff + wn + nt * 8 + 2 * tg;
            __nv_bfloat162 p0 = __floats2bfloat162_rn(acc[mt][nt][0], acc[mt][nt][1]);
            __nv_bfloat162 p1 = __floats2bfloat162_rn(acc[mt][nt][2], acc[mt][nt][3]);
            *reinterpret_cast<unsigned*>(dstbase + (size_t)row0 * rowStride + col) =
                *reinterpret_cast<unsigned*>(&p0);
            *reinterpret_cast<unsigned*>(dstbase + (size_t)(row0 + 8) * rowStride + col) =
                *reinterpret_cast<unsigned*>(&p1);
        }
    }
}

__device__ __forceinline__ void epi_max(const float acc[4][4][4], int tid,
                                        int rowBase, int colBase) {
    const int lid = tid & 31, w = tid >> 5;
    const int wm = (w >> 2) * 64, wn = (w & 3) * 32;
    const int g = lid >> 2, tg = lid & 3;
    const int rb = rowBase + wm;
    const int cb = colBase + wn;

    #pragma unroll
    for (int mt = 0; mt < 4; mt++) {
        float r0 = -3.0e38f, r1 = -3.0e38f;
        #pragma unroll
        for (int nt = 0; nt < 4; nt++) {
            r0 = fmaxf(r0, fmaxf(acc[mt][nt][0], acc[mt][nt][1]));
            r1 = fmaxf(r1, fmaxf(acc[mt][nt][2], acc[mt][nt][3]));
        }
        r0 = fmaxf(r0, __shfl_xor_sync(0xffffffffu, r0, 1));
        r0 = fmaxf(r0, __shfl_xor_sync(0xffffffffu, r0, 2));
        r1 = fmaxf(r1, __shfl_xor_sync(0xffffffffu, r1, 1));
        r1 = fmaxf(r1, __shfl_xor_sync(0xffffffffu, r1, 2));
        if (tg == 0) {
            atomicMax(&g_rmax[rb + mt * 16 + g], encf(r0));
            atomicMax(&g_rmax[rb + mt * 16 + g + 8], encf(r1));
        }
    }
    #pragma unroll
    for (int nt = 0; nt < 4; nt++) {
        float c0 = -3.0e38f, c1 = -3.0e38f;
        #pragma unroll
        for (int mt = 0; mt < 4; mt++) {
            c0 = fmaxf(c0, fmaxf(acc[mt][nt][0], acc[mt][nt][2]));
            c1 = fmaxf(c1, fmaxf(acc[mt][nt][1], acc[mt][nt][3]));
        }
        #pragma unroll
        for (int s = 4; s < 32; s <<= 1) {
            c0 = fmaxf(c0, __shfl_xor_sync(0xffffffffu, c0, s));
            c1 = fmaxf(c1, __shfl_xor_sync(0xffffffffu, c1, s));
        }
        if (g == 0) {
            atomicMax(&g_cmax[cb + nt * 8 + 2 * tg], encf(c0));
            atomicMax(&g_cmax[cb + nt * 8 + 2 * tg + 1], encf(c1));
        }
    }
}

#define ACC_DECL_ZERO(acc) \
    float acc[4][4][4]; \
    _Pragma("unroll") for (int _i = 0; _i < 4; _i++) \
    _Pragma("unroll") for (int _j = 0; _j < 4; _j++) \
    _Pragma("unroll") for (int _r = 0; _r < 4; _r++) acc[_i][_j][_r] = 0.0f;

// ---------------- k0: convert fp32->bf16 + mean partials + aux ---------------
__global__ void __launch_bounds__(256) k0_convert(const float* __restrict__ q,
                                                  const float* __restrict__ a,
                                                  const float* __restrict__ U) {
    int bx = blockIdx.x;
    int tid = threadIdx.x;

    if (bx >= 1024) {
        int bz = bx - 1024;
        if (bz < 64) {
            int i0 = (bz * 256 + tid) * 2;
            g_rmax[i0] = 0u; g_rmax[i0 + 1] = 0u;
            g_cmax[i0] = 0u; g_cmax[i0 + 1] = 0u;
            if (bz == 0 && tid == 0) g_need_full = 0;
        } else if (bz < 68) {
            int blk = bz - 64;   // Ut
            #pragma unroll 4
            for (int it = 0; it < 64; it++) {
                int i = blk * 16384 + it * 256 + tid;
                int d = i >> 8, e = i & 255;
                g_Ut[e * DD + d] = __float2bfloat16(U[i]);
            }
        } else {
            int blk = bz - 68;   // Ub (straight)
            #pragma unroll 4
            for (int it = 0; it < 64; it++) {
                int i = blk * 16384 + it * 256 + tid;
                g_Ub[i] = __float2bfloat16(U[i]);
            }
        }
        return;
    }

    int tensor = bx >> 9;
    int local = bx & 511;
    int b = local >> 5;
    int chunk = local & 31;   // 64-row chunk
    const float4* src = (const float4*)((tensor ? a : q) +
                        ((size_t)b * TT + (size_t)chunk * 64) * DD);
    uint2* dst = (uint2*)((tensor ? g_ab : g_qb) +
                 ((size_t)b * TT + (size_t)chunk * 64) * DD);

    const int dvec = tid & 63;          // float4 index within row
    const int rg = tid >> 6;            // row group 0..3
    float4 s = make_float4(0.f, 0.f, 0.f, 0.f);
    #pragma unroll 4
    for (int it = 0; it < 16; it++) {
        int row = it * 4 + rg;
        float4 v = src[(size_t)row * 64 + dvec];
        s.x += v.x; s.y += v.y; s.z += v.z; s.w += v.w;
        __nv_bfloat162 lo = __floats2bfloat162_rn(v.x, v.y);
        __nv_bfloat162 hi = __floats2bfloat162_rn(v.z, v.w);
        uint2 o;
        o.x = *reinterpret_cast<unsigned*>(&lo);
        o.y = *reinterpret_cast<unsigned*>(&hi);
        dst[(size_t)row * 64 + dvec] = o;
    }
    float4* mp = (float4*)&g_meanpart[((size_t)bx * 4 + rg) * DD];
    mp[dvec] = s;
}

// ---------------- kWqa: kW + k1a GEMM tiles + mean stage-1 (one launch) -------
__global__ void __launch_bounds__(256, 2) kWqa() {
    extern __shared__ char sm[];
    int tid = threadIdx.x;
    int bid = blockIdx.x;

    if (bid >= 128) {
        int v = bid - 128;   // 0..255
        float s = 0.0f;
        #pragma unroll
        for (int j = 0; j < 16; j++)
            s += g_meanpart[(size_t)(v * 16 + j) * DD + tid];
        g_mean2[(size_t)v * DD + tid] = s;
        return;
    }

    uint32_t smb = smem_u32(sm);
    int b = bid >> 3;
    int s = bid & 7;

    ACC_DECL_ZERO(acc);
    if (s < 4) {
        int tileM = s >> 1, tileN = s & 1;
        gemm_mainloop(smb, g_ab + ((size_t)b * TT + (size_t)tileM * 128) * DD,
                      g_Ub + (size_t)tileN * 128 * DD, tid, acc);
        epi_store_bf16(acc, tid, g_Wt + (size_t)b * 256 * DD,
                       tileM * 128, tileN * 128, DD);
    } else {
        int mi = (s - 4) >> 1, tileN = (s - 4) & 1;
        gemm_mainloop(smb, g_qb + (size_t)(b * 16 + mi) * 128 * DD,
                      g_Ut + (size_t)tileN * 128 * DD, tid, acc);
        epi_store_bf16(acc, tid, g_qU, (b * 16 + mi) * 128, tileN * 128, DD);
    }
}

// ---------------- kCert: kG_sample + col-cert (one launch, 960 CTAs) ----------
__global__ void __launch_bounds__(256, 2) kCert() {
    extern __shared__ char sm[];
    uint32_t smb = smem_u32(sm);
    int tid = threadIdx.x;
    int b = blockIdx.x / 60;
    int s = blockIdx.x % 60;

    ACC_DECL_ZERO(acc);
    if (s < 32) {
        int j = s >> 1, tileN = s & 1;
        gemm_mainloop(smb, g_qb + (size_t)(b * 16 + j) * 128 * DD,
                      g_Wt + (size_t)b * 256 * DD + (size_t)tileN * 128 * DD, tid, acc);
        epi_max(acc, tid, (b * 16 + j) * 128, b * TT + tileN * 128);
    } else {
        int g = s - 32;
        int nj = 2 + (g >> 1), mi = g & 1;
        gemm_mainloop(smb, g_qU + ((size_t)b * TT + (size_t)mi * 128) * DD,
                      g_ab + ((size_t)b * TT + (size_t)nj * 128) * DD, tid, acc);
        epi_max(acc, tid, b * TT + mi * 128, b * TT + nj * 128);
    }
}

// ---------------- kCheck: certify saturation (64 CTAs, uint4 / thread) --------
__global__ void kCheck() {
    int base = (blockIdx.x * 256 + threadIdx.x) * 4;   // 0..65532, 4-aligned
    const uint4* src = (base < BB * TT)
        ? (const uint4*)&g_rmax[base]
        : (const uint4*)&g_cmax[base - BB * TT];
    uint4 v0 = src[0];
    unsigned m = min(min(v0.x, v0.y), min(v0.z, v0.w));
    if (decf(m) < CERT_THRESH) atomicOr(&g_need_full, 1);
}

// ---------------- gated fallback: complete qU (7 tiles per CTA) ---------------
__global__ void __launch_bounds__(256, 2) k1_qU_gated() {
    if (g_need_full == 0) return;
    extern __shared__ char sm[];
    uint32_t smb = smem_u32(sm);
    int tid = threadIdx.x;
    int tileN = blockIdx.x & 1;
    int group = blockIdx.x >> 1;   // 0..31
    for (int i = 0; i < 7; i++) {
        int y = group * 7 + i;     // 0..223
        int tileM = (y / 14) * 16 + 2 + (y % 14);
        ACC_DECL_ZERO(acc);
        gemm_mainloop(smb, g_qb + (size_t)tileM * 128 * DD,
                      g_Ut + (size_t)tileN * 128 * DD, tid, acc);
        epi_store_bf16(acc, tid, g_qU, tileM * 128, tileN * 128, DD);
        __syncthreads();
    }
}

// ---------------- gated fallback: remaining G tiles (7 per CTA) ----------------
__global__ void __launch_bounds__(256, 2) k2_gated() {
    if (g_need_full == 0) return;
    extern __shared__ char sm[];
    uint32_t smb = smem_u32(sm);
    int tid = threadIdx.x;
    int nj = blockIdx.x + 2;
    int yy = blockIdx.y;           // 0..1
    int b  = blockIdx.z;
    for (int i = 0; i < 7; i++) {
        int mi = 2 + yy * 7 + i;   // 2..15
        ACC_DECL_ZERO(acc);
        gemm_mainloop(smb, g_qU + ((size_t)b * TT + (size_t)mi * 128) * DD,
                      g_ab + ((size_t)b * TT + (size_t)nj * 128) * DD, tid, acc);
        epi_max(acc, tid, b * TT + mi * 128, b * TT + nj * 128);
        __syncthreads();
    }
}

// ---------------- kOutFinal: certified means OR fallback softmax+pool ---------
__global__ void kOutFinal(const float* __restrict__ q, const float* __restrict__ a,
                          float* __restrict__ out) {
    __shared__ float ws[TT];
    __shared__ float red[256];
    int tid = threadIdx.x;
    int which = blockIdx.x >> 4;
    int b = blockIdx.x & 15;

    if (g_need_full == 0) {
        int base = which * 128 + b * 8;
        float s = 0.0f;
        #pragma unroll
        for (int j = 0; j < 8; j++) s += g_mean2[(size_t)(base + j) * DD + tid];
        out[which * BB * DD + b * DD + tid] = s * (1.0f / (float)TT);
        return;
    }

    const unsigned* src = (which ? g_cmax : g_rmax) + b * TT;
    float tv[8];
    #pragma unroll
    for (int i = 0; i < 8; i++) tv[i] = tanhf(decf(src[i * 256 + tid]));

    float lm = tv[0];
    #pragma unroll
    for (int i = 1; i < 8; i++) lm = fmaxf(lm, tv[i]);
    red[tid] = lm;
    __syncthreads();
    for (int s = 128; s > 0; s >>= 1) {
        if (tid < s) red[tid] = fmaxf(red[tid], red[tid + s]);
        __syncthreads();
    }
    float mx = red[0];
    __syncthreads();

    float ls = 0.0f;
    #pragma unroll
    for (int i = 0; i < 8; i++) ls += expf(tv[i] - mx);
    red[tid] = ls;
    __syncthreads();
    for (int s = 128; s > 0; s >>= 1) {
        if (tid < s) red[tid] += red[tid + s];
        __syncthreads();
    }
    float inv = 1.0f / red[0];
    __syncthreads();

    #pragma unroll
    for (int i = 0; i < 8; i++) ws[i * 256 + tid] = expf(tv[i] - mx) * inv;
    __syncthreads();

    const float* basep = (which ? a : q) + (size_t)b * TT * DD + tid;
    float acc = 0.0f;
    for (int t = 0; t < TT; t++) acc += ws[t] * basep[(size_t)t * DD];
    out[which * BB * DD + b * DD + tid] = acc;
}

// ---------------- launch ------------------------------------------------------
extern "C" void kernel_launch(void* const* d_in, const int* in_sizes, int n_in,
                              void* d_out, int out_size) {
    int ui = 2;
    for (int i = 0; i < n_in; i++)
        if (in_sizes[i] == DD * DD) ui = i;
    const float* ptrs[3];
    int k = 0;
    for (int i = 0; i < n_in && k < 3; i++)
        if (i != ui) ptrs[k++] = (const float*)d_in[i];
    const float* q = ptrs[0];
    const float* a = ptrs[1];
    const float* U = (const float*)d_in[ui];
    float* out = (float*)d_out;

    static int init_done = 0;
    if (!init_done) {
        cudaFuncSetAttribute(kWqa,        cudaFuncAttributeMaxDynamicSharedMemorySize, GEMM_SMEM);
        cudaFuncSetAttribute(kCert,       cudaFuncAttributeMaxDynamicSharedMemorySize, GEMM_SMEM);
        cudaFuncSetAttribute(k1_qU_gated, cudaFuncAttributeMaxDynamicSharedMemorySize, GEMM_SMEM);
        cudaFuncSetAttribute(k2_gated,    cudaFuncAttributeMaxDynamicSharedMemorySize, GEMM_SMEM);
        init_done = 1;
    }

    // converts + mean partials + U^T/U + zero maxes (no-smem, high occupancy)
    k0_convert<<<1096, 256>>>(q, a, U);
    // Wt tiles + qU rows {0,1}/batch + mean stage-1 filling idle SMs
    kWqa<<<384, 256, GEMM_SMEM>>>();
    // kG_sample + col-cert (merged, 960 CTAs)
    kCert<<<960, 256, GEMM_SMEM>>>();
    // certification check (64 CTAs, vectorized)
    kCheck<<<64, 256>>>();
    // fallback GEMMs (self-disabled when certified; loop-tiled dispatch)
    k1_qU_gated<<<64, 256, GEMM_SMEM>>>();
    k2_gated<<<dim3(14, 2, 16), 256, GEMM_SMEM>>>();
    // final output: certified means OR fallback softmax+pool
    kOutFinal<<<32, 256>>>(q, a, out);
    (void)out_size;
}

// round 16
// speedup vs baseline: 1.7572x; 1.2197x over previous
#include <cuda_runtime.h>
#include <cuda_bf16.h>
#include <stdint.h>
#include <math.h>

#define BB 16
#define TT 2048
#define DD 256

// Certification threshold. If every row/col max m has computed bf16 bound
// >= 6.5, then true m >= 6.0, so tanh(m) >= 1 - 2e^{-12} = 1 - 1.2e-5.
// Softmax over 2048 values all within eps of 1.0 has weights within ~2*eps
// RELATIVE of uniform, so the output deviates from the exact mean by ~2.4e-5
// relative -- and the reference sits in the same eps-ball. Threshold 6.5
// includes >=0.5 margin for bf16-GEMM bound error. (Previous 9.6 demanded
// exact fp32 saturation; that exactness is unnecessary at rel_err 1e-3.)
#define CERT_THRESH 6.5f

// ---------------- scratch (static __device__ arrays; no runtime allocation) ----
__device__ __nv_bfloat16 g_qb[BB*TT*DD];    // q in bf16
__device__ __nv_bfloat16 g_ab[BB*TT*DD];    // a in bf16
__device__ __nv_bfloat16 g_Ut[DD*DD];       // U^T in bf16 (Ut[e][d] = U[d][e])
__device__ __nv_bfloat16 g_Ub[DD*DD];       // U in bf16 (row-major)
__device__ __nv_bfloat16 g_qU[BB*TT*DD];    // qU in bf16 (rows mi=0/batch + gated rest)
__device__ __nv_bfloat16 g_Wt[BB*128*DD];   // Wt[b][j][d], j = a-rows 0..127
__device__ unsigned      g_rmax[BB*TT];     // encoded float max per q-row
__device__ unsigned      g_cmax[BB*TT];     // encoded float max per a-col
__device__ float         g_meanpart[1024*4*DD]; // per-(chunk,rowgroup) mean partials
__device__ float         g_mean2[256*DD];   // stage-1 reduced mean partials
__device__ int           g_need_full;       // 0 = certified (means exact)

// ---------------- helpers ----------------
__device__ __forceinline__ uint32_t smem_u32(const void* p) {
    uint32_t r;
    asm("{ .reg .u64 t; cvta.to.shared.u64 t, %1; cvt.u32.u64 %0, t; }"
        : "=r"(r) : "l"(p));
    return r;
}

__device__ __forceinline__ void cpasync16(uint32_t s, const void* g) {
    asm volatile("cp.async.cg.shared.global [%0], [%1], 16;" :: "r"(s), "l"(g) : "memory");
}
#define CP_COMMIT() asm volatile("cp.async.commit_group;" ::: "memory")
#define CP_WAIT0()  asm volatile("cp.async.wait_group 0;" ::: "memory")

__device__ __forceinline__ void ldmx4(uint32_t addr, uint32_t& r0, uint32_t& r1,
                                      uint32_t& r2, uint32_t& r3) {
    asm volatile("ldmatrix.sync.aligned.m8n8.x4.shared.b16 {%0,%1,%2,%3}, [%4];"
                 : "=r"(r0), "=r"(r1), "=r"(r2), "=r"(r3) : "r"(addr));
}

__device__ __forceinline__ void mma16816(float* c, uint32_t a0, uint32_t a1,
                                         uint32_t a2, uint32_t a3,
                                         uint32_t b0, uint32_t b1) {
    asm volatile(
        "mma.sync.aligned.m16n8k16.row.col.f32.bf16.bf16.f32 "
        "{%0,%1,%2,%3}, {%4,%5,%6,%7}, {%8,%9}, {%0,%1,%2,%3};"
        : "+f"(c[0]), "+f"(c[1]), "+f"(c[2]), "+f"(c[3])
        : "r"(a0), "r"(a1), "r"(a2), "r"(a3), "r"(b0), "r"(b1));
}

__device__ __forceinline__ unsigned encf(float f) {
    unsigned u = __float_as_uint(f);
    return (u & 0x80000000u) ? ~u : (u | 0x80000000u);
}
__device__ __forceinline__ float decf(unsigned e) {
    unsigned u = (e & 0x80000000u) ? (e & 0x7FFFFFFFu) : ~e;
    return __uint_as_float(u);
}

// ---------------- GEMM core: C[128x128] = A[128x256] * B[128x256]^T -----------
#define GEMM_SMEM 65536

__device__ __forceinline__ void load_chunk(uint32_t smb, int buf,
                                           const __nv_bfloat16* __restrict__ A,
                                           const __nv_bfloat16* __restrict__ Bm,
                                           int ck, int tid) {
    const __nv_bfloat16* Ac = A + ck * 64;
    const __nv_bfloat16* Bc = Bm + ck * 64;
    #pragma unroll
    for (int i = 0; i < 4; i++) {
        int v = tid + i * 256;
        int row = v >> 3, kv = v & 7;
        uint32_t o = (uint32_t)row * 128u + (uint32_t)((kv ^ (row & 7)) * 16);
        const size_t goff = (size_t)row * DD + (size_t)kv * 8;
        cpasync16(smb + buf * 16384 + o, Ac + goff);
        cpasync16(smb + 32768 + buf * 16384 + o, Bc + goff);
    }
}

// Single-sync double-buffered pipeline (proven config).
__device__ __forceinline__ void gemm_mainloop(uint32_t smb, const __nv_bfloat16* A,
                                              const __nv_bfloat16* Bm, int tid,
                                              float acc[4][4][4]) {
    const int lid = tid & 31, w = tid >> 5;
    const int wm = (w >> 2) * 64, wn = (w & 3) * 32;
    const int lrow = lid & 15;
    const uint32_t khalf = (uint32_t)(lid >> 4) * 16u;
    const uint32_t rxor = (uint32_t)(lrow & 7) * 16u;

    uint32_t arow[4], brow[2];
    #pragma unroll
    for (int mt = 0; mt < 4; mt++) arow[mt] = (uint32_t)(wm + mt * 16 + lrow) * 128u;
    #pragma unroll
    for (int np = 0; np < 2; np++) brow[np] = (uint32_t)(wn + np * 16 + lrow) * 128u;

    load_chunk(smb, 0, A, Bm, 0, tid);
    CP_COMMIT();

    #pragma unroll
    for (int ck = 0; ck < 4; ck++) {
        CP_WAIT0();
        __syncthreads();
        if (ck + 1 < 4) {
            load_chunk(smb, (ck + 1) & 1, A, Bm, ck + 1, tid);
            CP_COMMIT();
        }

        const uint32_t abase = smb + (ck & 1) * 16384;
        const uint32_t bbase = smb + 32768 + (ck & 1) * 16384;

        #pragma unroll
        for (int kk = 0; kk < 4; kk++) {
            const uint32_t kswz = ((uint32_t)kk * 32u + khalf) ^ rxor;
            uint32_t a[4][4];
            #pragma unroll
            for (int mt = 0; mt < 4; mt++)
                ldmx4(abase + arow[mt] + kswz, a[mt][0], a[mt][1], a[mt][2], a[mt][3]);
            uint32_t b[4][2];
            #pragma unroll
            for (int np = 0; np < 2; np++) {
                uint32_t r0, r1, r2, r3;
                ldmx4(bbase + brow[np] + kswz, r0, r1, r2, r3);
                b[np * 2 + 0][0] = r0; b[np * 2 + 0][1] = r2;
                b[np * 2 + 1][0] = r1; b[np * 2 + 1][1] = r3;
            }
            #pragma unroll
            for (int mt = 0; mt < 4; mt++)
                #pragma unroll
                for (int nt = 0; nt < 4; nt++)
                    mma16816(acc[mt][nt], a[mt][0], a[mt][1], a[mt][2], a[mt][3],
                             b[nt][0], b[nt][1]);
        }
    }
}

// shared epilogues ------------------------------------------------------------
__device__ __forceinline__ void epi_store_bf16(const float acc[4][4][4], int tid,
                                               __nv_bfloat16* dstbase, int rowOff,
                                               int colOff, int rowStride) {
    const int lid = tid & 31, w = tid >> 5;
    const int wm = (w >> 2) * 64, wn = (w & 3) * 32;
    const int g = lid >> 2, tg = lid & 3;
    #pragma unroll
    for (int mt = 0; mt < 4; mt++) {
        int row0 = rowOff + wm + mt * 16 + g;
        #pragma unroll
        for (int nt = 0; nt < 4; nt++) {
            int col = colOff + wn + nt * 8 + 2 * tg;
            __nv_bfloat162 p0 = __floats2bfloat162_rn(acc[mt][nt][0], acc[mt][nt][1]);
            __nv_bfloat162 p1 = __floats2bfloat162_rn(acc[mt][nt][2], acc[mt][nt][3]);
            *reinterpret_cast<unsigned*>(dstbase + (size_t)row0 * rowStride + col) =
                *reinterpret_cast<unsigned*>(&p0);
            *reinterpret_cast<unsigned*>(dstbase + (size_t)(row0 + 8) * rowStride + col) =
                *reinterpret_cast<unsigned*>(&p1);
        }
    }
}

__device__ __forceinline__ void epi_max(const float acc[4][4][4], int tid,
                                        int rowBase, int colBase) {
    const int lid = tid & 31, w = tid >> 5;
    const int wm = (w >> 2) * 64, wn = (w & 3) * 32;
    const int g = lid >> 2, tg = lid & 3;
    const int rb = rowBase + wm;
    const int cb = colBase + wn;

    #pragma unroll
    for (int mt = 0; mt < 4; mt++) {
        float r0 = -3.0e38f, r1 = -3.0e38f;
        #pragma unroll
        for (int nt = 0; nt < 4; nt++) {
            r0 = fmaxf(r0, fmaxf(acc[mt][nt][0], acc[mt][nt][1]));
            r1 = fmaxf(r1, fmaxf(acc[mt][nt][2], acc[mt][nt][3]));
        }
        r0 = fmaxf(r0, __shfl_xor_sync(0xffffffffu, r0, 1));
        r0 = fmaxf(r0, __shfl_xor_sync(0xffffffffu, r0, 2));
        r1 = fmaxf(r1, __shfl_xor_sync(0xffffffffu, r1, 1));
        r1 = fmaxf(r1, __shfl_xor_sync(0xffffffffu, r1, 2));
        if (tg == 0) {
            atomicMax(&g_rmax[rb + mt * 16 + g], encf(r0));
            atomicMax(&g_rmax[rb + mt * 16 + g + 8], encf(r1));
        }
    }
    #pragma unroll
    for (int nt = 0; nt < 4; nt++) {
        float c0 = -3.0e38f, c1 = -3.0e38f;
        #pragma unroll
        for (int mt = 0; mt < 4; mt++) {
            c0 = fmaxf(c0, fmaxf(acc[mt][nt][0], acc[mt][nt][2]));
            c1 = fmaxf(c1, fmaxf(acc[mt][nt][1], acc[mt][nt][3]));
        }
        #pragma unroll
        for (int s = 4; s < 32; s <<= 1) {
            c0 = fmaxf(c0, __shfl_xor_sync(0xffffffffu, c0, s));
            c1 = fmaxf(c1, __shfl_xor_sync(0xffffffffu, c1, s));
        }
        if (g == 0) {
            atomicMax(&g_cmax[cb + nt * 8 + 2 * tg], encf(c0));
            atomicMax(&g_cmax[cb + nt * 8 + 2 * tg + 1], encf(c1));
        }
    }
}

#define ACC_DECL_ZERO(acc) \
    float acc[4][4][4]; \
    _Pragma("unroll") for (int _i = 0; _i < 4; _i++) \
    _Pragma("unroll") for (int _j = 0; _j < 4; _j++) \
    _Pragma("unroll") for (int _r = 0; _r < 4; _r++) acc[_i][_j][_r] = 0.0f;

// ---------------- k0: convert fp32->bf16 + mean partials + aux ---------------
__global__ void __launch_bounds__(256) k0_convert(const float* __restrict__ q,
                                                  const float* __restrict__ a,
                                                  const float* __restrict__ U) {
    int bx = blockIdx.x;
    int tid = threadIdx.x;

    if (bx >= 1024) {
        int bz = bx - 1024;
        if (bz < 64) {
            int i0 = (bz * 256 + tid) * 2;
            g_rmax[i0] = 0u; g_rmax[i0 + 1] = 0u;
            g_cmax[i0] = 0u; g_cmax[i0 + 1] = 0u;
            if (bz == 0 && tid == 0) g_need_full = 0;
        } else if (bz < 68) {
            int blk = bz - 64;   // Ut
            #pragma unroll 4
            for (int it = 0; it < 64; it++) {
                int i = blk * 16384 + it * 256 + tid;
                int d = i >> 8, e = i & 255;
                g_Ut[e * DD + d] = __float2bfloat16(U[i]);
            }
        } else {
            int blk = bz - 68;   // Ub (straight)
            #pragma unroll 4
            for (int it = 0; it < 64; it++) {
                int i = blk * 16384 + it * 256 + tid;
                g_Ub[i] = __float2bfloat16(U[i]);
            }
        }
        return;
    }

    int tensor = bx >> 9;
    int local = bx & 511;
    int b = local >> 5;
    int chunk = local & 31;   // 64-row chunk
    const float4* src = (const float4*)((tensor ? a : q) +
                        ((size_t)b * TT + (size_t)chunk * 64) * DD);
    uint2* dst = (uint2*)((tensor ? g_ab : g_qb) +
                 ((size_t)b * TT + (size_t)chunk * 64) * DD);

    const int dvec = tid & 63;          // float4 index within row
    const int rg = tid >> 6;            // row group 0..3
    float4 s = make_float4(0.f, 0.f, 0.f, 0.f);
    #pragma unroll 4
    for (int it = 0; it < 16; it++) {
        int row = it * 4 + rg;
        float4 v = src[(size_t)row * 64 + dvec];
        s.x += v.x; s.y += v.y; s.z += v.z; s.w += v.w;
        __nv_bfloat162 lo = __floats2bfloat162_rn(v.x, v.y);
        __nv_bfloat162 hi = __floats2bfloat162_rn(v.z, v.w);
        uint2 o;
        o.x = *reinterpret_cast<unsigned*>(&lo);
        o.y = *reinterpret_cast<unsigned*>(&hi);
        dst[(size_t)row * 64 + dvec] = o;
    }
    float4* mp = (float4*)&g_meanpart[((size_t)bx * 4 + rg) * DD];
    mp[dvec] = s;
}

// ---------------- kWqa: kW(tileM=0) + k1a(mi=0) tiles + mean stage-1 ----------
// bid<64: b = bid>>2, s = bid&3. s<2: kW tile (tileM=0, tileN=s).
// s>=2: k1a tile (mi=0, tileN=s-2).
// bid in [64,320): mean stage-1 -- sum 16 meanpart slot-vectors -> g_mean2.
__global__ void __launch_bounds__(256, 2) kWqa() {
    extern __shared__ char sm[];
    int tid = threadIdx.x;
    int bid = blockIdx.x;

    if (bid >= 64) {
        int v = bid - 64;   // 0..255
        float s = 0.0f;
        #pragma unroll
        for (int j = 0; j < 16; j++)
            s += g_meanpart[(size_t)(v * 16 + j) * DD + tid];
        g_mean2[(size_t)v * DD + tid] = s;
        return;
    }

    uint32_t smb = smem_u32(sm);
    int b = bid >> 2;
    int s = bid & 3;

    ACC_DECL_ZERO(acc);
    if (s < 2) {
        int tileN = s;   // Wt[b] for a-rows 0..127, d block tileN
        gemm_mainloop(smb, g_ab + (size_t)b * TT * DD,
                      g_Ub + (size_t)tileN * 128 * DD, tid, acc);
        epi_store_bf16(acc, tid, g_Wt + (size_t)b * 128 * DD,
                       0, tileN * 128, DD);
    } else {
        int tileN = s - 2;   // qU rows b*16 (mi=0)
        gemm_mainloop(smb, g_qb + (size_t)(b * 16) * 128 * DD,
                      g_Ut + (size_t)tileN * 128 * DD, tid, acc);
        epi_store_bf16(acc, tid, g_qU, (b * 16) * 128, tileN * 128, DD);
    }
}

// ---------------- kCert: kG (128-col row samples, exact cols 0..127) +
//                   col-cert (cols 128..2047 sampled on q-rows 0..127) --------
// 496 CTAs: b = bid/31, s = bid%31. s<16: kG tile (q-row block j=s, cols
// 0..127 via Wt). s>=16: col-cert (mi=0, nb = 1 + (s-16)).
__global__ void __launch_bounds__(256, 2) kCert() {
    extern __shared__ char sm[];
    uint32_t smb = smem_u32(sm);
    int tid = threadIdx.x;
    int b = blockIdx.x / 31;
    int s = blockIdx.x % 31;

    ACC_DECL_ZERO(acc);
    if (s < 16) {
        int j = s;
        gemm_mainloop(smb, g_qb + (size_t)(b * 16 + j) * 128 * DD,
                      g_Wt + (size_t)b * 128 * DD, tid, acc);
        epi_max(acc, tid, (b * 16 + j) * 128, b * TT);
    } else {
        int nb = 1 + (s - 16);   // 1..15
        gemm_mainloop(smb, g_qU + (size_t)(b * 16) * 128 * DD,
                      g_ab + ((size_t)b * TT + (size_t)nb * 128) * DD, tid, acc);
        epi_max(acc, tid, b * TT, b * TT + nb * 128);
    }
}

// ---------------- kCheck: certify bounds (64 CTAs, uint4 / thread) ------------
__global__ void kCheck() {
    int base = (blockIdx.x * 256 + threadIdx.x) * 4;   // 0..65532, 4-aligned
    const uint4* src = (base < BB * TT)
        ? (const uint4*)&g_rmax[base]
        : (const uint4*)&g_cmax[base - BB * TT];
    uint4 v0 = src[0];
    unsigned m = min(min(v0.x, v0.y), min(v0.z, v0.w));
    if (decf(m) < CERT_THRESH) atomicOr(&g_need_full, 1);
}

// ---------------- gated fallback: complete qU mi=1..15 (5 tiles per CTA) ------
__global__ void __launch_bounds__(256, 2) k1_qU_gated() {
    if (g_need_full == 0) return;
    extern __shared__ char sm[];
    uint32_t smb = smem_u32(sm);
    int tid = threadIdx.x;
    int tileN = blockIdx.x & 1;
    int group = blockIdx.x >> 1;   // 0..47
    for (int i = 0; i < 5; i++) {
        int y = group * 5 + i;     // 0..239
        int tileM = (y / 15) * 16 + 1 + (y % 15);
        ACC_DECL_ZERO(acc);
        gemm_mainloop(smb, g_qb + (size_t)tileM * 128 * DD,
                      g_Ut + (size_t)tileN * 128 * DD, tid, acc);
        epi_store_bf16(acc, tid, g_qU, tileM * 128, tileN * 128, DD);
        __syncthreads();
    }
}

// ---------------- gated fallback: tiles (mi 1..15, nb 1..15), 15 per CTA ------
__global__ void __launch_bounds__(256, 2) k2_gated() {
    if (g_need_full == 0) return;
    extern __shared__ char sm[];
    uint32_t smb = smem_u32(sm);
    int tid = threadIdx.x;
    int nb = blockIdx.x + 1;       // 1..15
    int b  = blockIdx.y;
    for (int i = 0; i < 15; i++) {
        int mi = 1 + i;            // 1..15
        ACC_DECL_ZERO(acc);
        gemm_mainloop(smb, g_qU + ((size_t)b * TT + (size_t)mi * 128) * DD,
                      g_ab + ((size_t)b * TT + (size_t)nb * 128) * DD, tid, acc);
        epi_max(acc, tid, b * TT + mi * 128, b * TT + nb * 128);
        __syncthreads();
    }
}

// ---------------- kOutFinal: certified means OR fallback softmax+pool ---------
__global__ void kOutFinal(const float* __restrict__ q, const float* __restrict__ a,
                          float* __restrict__ out) {
    __shared__ float ws[TT];
    __shared__ float red[256];
    int tid = threadIdx.x;
    int which = blockIdx.x >> 4;
    int b = blockIdx.x & 15;

    if (g_need_full == 0) {
        int base = which * 128 + b * 8;
        float s = 0.0f;
        #pragma unroll
        for (int j = 0; j < 8; j++) s += g_mean2[(size_t)(base + j) * DD + tid];
        out[which * BB * DD + b * DD + tid] = s * (1.0f / (float)TT);
        return;
    }

    const unsigned* src = (which ? g_cmax : g_rmax) + b * TT;
    float tv[8];
    #pragma unroll
    for (int i = 0; i < 8; i++) tv[i] = tanhf(decf(src[i * 256 + tid]));

    float lm = tv[0];
    #pragma unroll
    for (int i = 1; i < 8; i++) lm = fmaxf(lm, tv[i]);
    red[tid] = lm;
    __syncthreads();
    for (int s = 128; s > 0; s >>= 1) {
        if (tid < s) red[tid] = fmaxf(red[tid], red[tid + s]);
        __syncthreads();
    }
    float mx = red[0];
    __syncthreads();

    float ls = 0.0f;
    #pragma unroll
    for (int i = 0; i < 8; i++) ls += expf(tv[i] - mx);
    red[tid] = ls;
    __syncthreads();
    for (int s = 128; s > 0; s >>= 1) {
        if (tid < s) red[tid] += red[tid + s];
        __syncthreads();
    }
    float inv = 1.0f / red[0];
    __syncthreads();

    #pragma unroll
    for (int i = 0; i < 8; i++) ws[i * 256 + tid] = expf(tv[i] - mx) * inv;
    __syncthreads();

    const float* basep = (which ? a : q) + (size_t)b * TT * DD + tid;
    float acc = 0.0f;
    for (int t = 0; t < TT; t++) acc += ws[t] * basep[(size_t)t * DD];
    out[which * BB * DD + b * DD + tid] = acc;
}

// ---------------- launch ------------------------------------------------------
extern "C" void kernel_launch(void* const* d_in, const int* in_sizes, int n_in,
                              void* d_out, int out_size) {
    int ui = 2;
    for (int i = 0; i < n_in; i++)
        if (in_sizes[i] == DD * DD) ui = i;
    const float* ptrs[3];
    int k = 0;
    for (int i = 0; i < n_in && k < 3; i++)
        if (i != ui) ptrs[k++] = (const float*)d_in[i];
    const float* q = ptrs[0];
    const float* a = ptrs[1];
    const float* U = (const float*)d_in[ui];
    float* out = (float*)d_out;

    static int init_done = 0;
    if (!init_done) {
        cudaFuncSetAttribute(kWqa,        cudaFuncAttributeMaxDynamicSharedMemorySize, GEMM_SMEM);
        cudaFuncSetAttribute(kCert,       cudaFuncAttributeMaxDynamicSharedMemorySize, GEMM_SMEM);
        cudaFuncSetAttribute(k1_qU_gated, cudaFuncAttributeMaxDynamicSharedMemorySize, GEMM_SMEM);
        cudaFuncSetAttribute(k2_gated,    cudaFuncAttributeMaxDynamicSharedMemorySize, GEMM_SMEM);
        init_done = 1;
    }

    // converts + mean partials + U^T/U + zero maxes (no-smem, high occupancy)
    k0_convert<<<1096, 256>>>(q, a, U);
    // Wt (a-rows 0..127) + qU (mi=0) + mean stage-1 filling idle SMs
    kWqa<<<320, 256, GEMM_SMEM>>>();
    // kG (row samples on 128 cols; exact col maxes 0..127) + col-cert (496 CTAs)
    kCert<<<496, 256, GEMM_SMEM>>>();
    // certification check (64 CTAs, vectorized)
    kCheck<<<64, 256>>>();
    // fallback GEMMs (self-disabled when certified; loop-tiled dispatch)
    k1_qU_gated<<<96, 256, GEMM_SMEM>>>();
    k2_gated<<<dim3(15, 16), 256, GEMM_SMEM>>>();
    // final output: certified means OR fallback softmax+pool
    kOutFinal<<<32, 256>>>(q, a, out);
    (void)out_size;
}